// round 8
// baseline (speedup 1.0000x reference)
#include <cuda_runtime.h>
#include <cuda_bf16.h>
#include <math.h>
#include <stdint.h>

#define NB 16
#define NTE 64
#define NTD 32
#define NE 256
#define NH 512
#define NG 2048
#define NV 90000
#define NVP 90112
#define NEGV (-1e9f)
#define PX 18   // smem pitch (floats) for [k][b] tiles

typedef unsigned long long u64;

// ---------------- device scratch (static, no allocation) ----------------
__device__ float g_qemb[NB*NTE*NE];
__device__ float g_remb[NB*NTD*NE];
__device__ float g_h[2][NB*NH];
__device__ float g_c[2][NB*NH];
__device__ float g_attn[NB*NH];
__device__ float g_encout[NB*NTE*NH];
__device__ float g_keys[NB*NTE*NH];
__device__ float g_pq[NB*NH];
__device__ float g_ctx[NB*NH];
__device__ int   g_outrow[NB*NTD];
__device__ int   g_rowpos[NB*NTD];
__device__ int   g_nrows;
__device__ float g_W2e[768*NG];
__device__ float g_W2d[1280*NG];
// two-level barrier state: 8 counter lines (128B apart) + 1 epoch word, per kernel
__device__ unsigned g_cntE[8*32];
__device__ unsigned g_epochE;
__device__ unsigned g_cntD[8*32];
__device__ unsigned g_epochD;
__device__ __nv_bfloat16 g_Wphi[(size_t)NVP*NH];   // [v][k]
__device__ __nv_bfloat16 g_Wplo[(size_t)NVP*NH];
__device__ __nv_bfloat16 g_Ahi[512*NH];            // [m][k], zero-padded
__device__ __nv_bfloat16 g_Alo[512*NH];

__device__ __forceinline__ float sigf(float x) { return 1.0f / (1.0f + expf(-x)); }

__device__ __forceinline__ u64 packdup(float v) {
    u64 r;
    asm("mov.b64 %0, {%1, %1};" : "=l"(r) : "r"(__float_as_uint(v)));
    return r;
}
__device__ __forceinline__ void fma2(u64& d, u64 a, u64 b) {
    asm("fma.rn.f32x2 %0, %1, %2, %0;" : "+l"(d) : "l"(a), "l"(b));
}
__device__ __forceinline__ void unpack2(u64 v, float& lo, float& hi) {
    unsigned l, h;
    asm("mov.b64 {%0, %1}, %2;" : "=r"(l), "=r"(h) : "l"(v));
    lo = __uint_as_float(l); hi = __uint_as_float(h);
}
__device__ __forceinline__ uint32_t smem_u32(const void* p) {
    uint32_t a;
    asm("{ .reg .u64 t; cvta.to.shared.u64 t, %1; cvt.u32.u64 %0, t; }" : "=r"(a) : "l"(p));
    return a;
}

// ---------------- two-level grid barrier ----------------
// Arrivals spread over 8 lines via red.release (no RMW contention with pollers).
// CTA 0 aggregates and publishes a monotone epoch; others read-only poll epoch.
__device__ __forceinline__ void gbar2(unsigned* cnt, unsigned* epoch, int c, unsigned idx) {
    __syncthreads();
    if (threadIdx.x == 0) {
        unsigned* line = cnt + ((c & 7) << 5);
        asm volatile("red.release.gpu.global.add.u32 [%0], 1;" :: "l"(line) : "memory");
        if (c == 0) {
            unsigned need = idx * 128u;
            for (;;) {
                unsigned s = 0;
                #pragma unroll
                for (int i = 0; i < 8; i++) {
                    unsigned v;
                    asm volatile("ld.global.acquire.gpu.u32 %0, [%1];"
                                 : "=r"(v) : "l"(cnt + (i << 5)) : "memory");
                    s += v;
                }
                if (s >= need) break;
            }
            asm volatile("st.global.release.gpu.u32 [%0], %1;" :: "l"(epoch), "r"(idx) : "memory");
        } else {
            unsigned v;
            do {
                asm volatile("ld.global.acquire.gpu.u32 %0, [%1];" : "=r"(v) : "l"(epoch) : "memory");
            } while (v < idx);
        }
    }
    __syncthreads();
}

// ---------------- prep ----------------
__global__ void prep_kernel(const int* __restrict__ enc_in, const int* __restrict__ dec_in,
                            const int* __restrict__ dlen, const float* __restrict__ emb)
{
    int idx = blockIdx.x * blockDim.x + threadIdx.x;
    int stride = gridDim.x * blockDim.x;
    for (int i = idx; i < NB*NTE*NE; i += stride) {
        int e = i & (NE - 1); int bt = i >> 8;
        g_qemb[i] = emb[(size_t)enc_in[bt] * NE + e];
    }
    for (int i = idx; i < NB*NTD*NE; i += stride) {
        int e = i & (NE - 1); int bt = i >> 8;
        g_remb[i] = emb[(size_t)dec_in[bt] * NE + e];
    }
    for (int i = idx; i < NB*NH; i += stride) {
        g_h[0][i] = 0.f; g_c[0][i] = 0.f; g_attn[i] = 0.f;
    }
    __nv_bfloat16 z = __float2bfloat16(0.f);
    for (int i = idx; i < 512*NH; i += stride) { g_Ahi[i] = z; g_Alo[i] = z; }
    if (idx < 8*32) { g_cntE[idx] = 0u; g_cntD[idx] = 0u; }
    if (idx == 0) {
        g_epochE = 0u; g_epochD = 0u;
        int n = 0;
        for (int b = 0; b < NB; b++) {
            int L = dlen[b]; if (L > NTD) L = NTD; if (L < 0) L = 0;
            for (int t2 = 0; t2 < NTD; t2++) {
                if (t2 < L) { g_outrow[n] = b*NTD + t2; g_rowpos[b*NTD + t2] = n; n++; }
                else g_rowpos[b*NTD + t2] = -1;
            }
        }
        g_nrows = n;
    }
}

// ---------------- permute LSTM weights: W2[k][blk*16 + jl*4 + q] ----------------
__global__ void permW_kernel(const float* __restrict__ We, const float* __restrict__ Wd)
{
    int idx = blockIdx.x * blockDim.x + threadIdx.x;
    int stride = gridDim.x * blockDim.x;
    for (int i = idx; i < 768*NG; i += stride) {
        int k = i >> 11, g2 = i & (NG - 1);
        int blk = g2 >> 4, x = g2 & 15, jl = x >> 2, q = x & 3;
        g_W2e[i] = We[(size_t)k*NG + q*NH + (blk << 2) + jl];
    }
    for (int i = idx; i < 1280*NG; i += stride) {
        int k = i >> 11, g2 = i & (NG - 1);
        int blk = g2 >> 4, x = g2 & 15, jl = x >> 2, q = x & 3;
        g_W2d[i] = Wd[(size_t)k*NG + q*NH + (blk << 2) + jl];
    }
}

__global__ void zero_kernel(float4* __restrict__ out, int n4)
{
    int idx = blockIdx.x * blockDim.x + threadIdx.x;
    int stride = gridDim.x * blockDim.x;
    float4 z = make_float4(0.f, 0.f, 0.f, 0.f);
    for (int i = idx; i < n4; i += stride) out[i] = z;
}

// ---------------- W_proj -> transposed bf16 hi/lo: Wt[v][k] ----------------
__global__ void wconv_kernel(const float* __restrict__ Wp)
{
    __shared__ float tile[64][65];
    int v0 = blockIdx.x * 64, k0 = blockIdx.y * 64;
    int tid = threadIdx.x;
    for (int i = tid; i < 4096; i += 256) {
        int kk = i >> 6, vv = i & 63;
        int v = v0 + vv;
        tile[kk][vv] = (v < NV) ? Wp[(size_t)(k0 + kk)*NV + v] : 0.f;
    }
    __syncthreads();
    for (int i = tid; i < 4096; i += 256) {
        int vv = i >> 6, kk = i & 63;
        float x = tile[kk][vv];
        __nv_bfloat16 hi = __float2bfloat16(x);
        float r = x - __bfloat162float(hi);
        size_t o = (size_t)(v0 + vv)*NH + k0 + kk;
        g_Wphi[o] = hi;
        g_Wplo[o] = __float2bfloat16(r);
    }
}

// ---------------- persistent encoder ----------------
__global__ void __launch_bounds__(256, 1)
enc_mega(const float* __restrict__ bias, const int* __restrict__ elen)
{
    extern __shared__ float sm[];
    float* xs = sm;                 // [768][PX]
    float* zp = sm + 768*PX;        // [256][PX]
    float* zz = zp + 256*PX;        // [256]

    int tid = threadIdx.x;
    int c = blockIdx.x;
    int gl = tid & 15, s = tid >> 4;
    int k0 = s * 48;

    float wreg[48];
    {
        const float* Wp = g_W2e + (c << 4) + gl;
        #pragma unroll
        for (int kk = 0; kk < 48; kk++) wreg[kk] = Wp[(size_t)(k0 + kk) * NG];
    }
    int g2r = tid >> 4;
    float bv = bias[(g2r & 3)*NH + (c << 2) + (g2r >> 2)];

    for (int t = 0; t < NTE; t++) {
        const float* h_in  = g_h[t & 1];
        const float* c_in  = g_c[t & 1];
        float* h_out = g_h[(t + 1) & 1];
        float* c_out = g_c[(t + 1) & 1];

        #pragma unroll
        for (int b = 0; b < 16; b++)
            for (int k = tid; k < 768; k += 256) {
                float v = (k < NE) ? g_qemb[(b*NTE + t)*NE + k]
                                   : __ldcg(&h_in[b*NH + (k - NE)]);
                xs[k*PX + b] = v;
            }
        __syncthreads();

        u64 acc[8];
        #pragma unroll
        for (int p = 0; p < 8; p++) acc[p] = 0ULL;
        #pragma unroll
        for (int kk = 0; kk < 48; kk++) {
            u64 w2 = packdup(wreg[kk]);
            const u64* xk = (const u64*)(xs + (k0 + kk)*PX);
            #pragma unroll
            for (int p = 0; p < 8; p++) fma2(acc[p], xk[p], w2);
        }
        #pragma unroll
        for (int p = 0; p < 8; p++) {
            float lo, hi; unpack2(acc[p], lo, hi);
            zp[tid*PX + 2*p]   = lo;
            zp[tid*PX + 2*p+1] = hi;
        }
        __syncthreads();

        {
            int g2 = tid >> 4, b = tid & 15;
            float sum = 0.f;
            #pragma unroll
            for (int ss = 0; ss < 16; ss++) sum += zp[(g2 + 16*ss)*PX + b];
            zz[g2*16 + b] = sum + bv;
        }
        __syncthreads();

        if (tid < 64) {
            int jl = tid >> 4, b = tid & 15;
            int jg = (c << 2) + jl;
            float iv = zz[(jl*4 + 0)*16 + b];
            float jv = zz[(jl*4 + 1)*16 + b];
            float fv = zz[(jl*4 + 2)*16 + b];
            float ov = zz[(jl*4 + 3)*16 + b];
            float cold = c_in[b*NH + jg];
            float c2 = cold * sigf(fv + 1.f) + sigf(iv) * tanhf(jv);
            float h2 = tanhf(c2) * sigf(ov);
            bool valid = t < elen[b];
            float hold = xs[(NE + jg)*PX + b];
            h_out[b*NH + jg] = valid ? h2 : hold;
            c_out[b*NH + jg] = valid ? c2 : cold;
            g_encout[((size_t)b*NTE + t)*NH + jg] = valid ? h2 : 0.f;
        }
        gbar2(g_cntE, &g_epochE, c, (unsigned)(t + 1));
    }
}

// ---------------- keys = enc_out @ W_mem ----------------
__global__ void keys_kernel(const float* __restrict__ Wm)
{
    extern __shared__ float sm[];
    const int KX = NH, KP = NH + 4;
    float* xs = sm;
    float* ws = sm + 16*KP;
    int tid = threadIdx.x;
    int cn = blockIdx.x;
    int cr = blockIdx.y;

    for (int i = tid; i < 16*KX; i += 256) {
        int rl = i >> 9, k = i & 511;
        xs[rl*KP + k] = g_encout[(cr*16 + rl)*NH + k];
    }
    for (int i = tid; i < 16*KX; i += 256) {
        int k = i >> 4, nl = i & 15;
        ws[nl*KP + k] = Wm[k*NH + cn*16 + nl];
    }
    __syncthreads();

    int nl = tid & 15, rl = tid >> 4;
    float a0 = 0.f, a1 = 0.f, a2 = 0.f, a3 = 0.f;
    const float* xp = xs + rl*KP;
    const float* wp = ws + nl*KP;
    #pragma unroll 8
    for (int k = 0; k < KX; k += 4) {
        float4 a = *(const float4*)(xp + k);
        float4 w = *(const float4*)(wp + k);
        a0 = fmaf(a.x, w.x, a0);
        a1 = fmaf(a.y, w.y, a1);
        a2 = fmaf(a.z, w.z, a2);
        a3 = fmaf(a.w, w.w, a3);
    }
    g_keys[(cr*16 + rl)*NH + cn*16 + nl] = (a0 + a1) + (a2 + a3);
}

// ---------------- persistent decoder ----------------
__global__ void __launch_bounds__(256, 1)
dec_mega(const float* __restrict__ bias, const float* __restrict__ Wq,
         const float* __restrict__ vatt, const float* __restrict__ Wa,
         const int* __restrict__ elen)
{
    extern __shared__ float sm[];
    float* xs  = sm;                    // [1280][PX]
    float* zp  = sm + 1280*PX;          // [256][PX]
    float* zz  = zp + 256*PX;           // [256]
    float* wqs = zz + 256;              // [512][4]
    float* was = wqs + 2048;            // [1024][4]
    float* pqv = sm;                    // phase3 aliases
    float* vsv = sm + 512;
    float* scv = sm + 1024;

    int tid = threadIdx.x;
    int c = blockIdx.x;
    int gl = tid & 15, s = tid >> 4;
    int k0 = s * 80;
    int n0 = c * 4;
    int bq = tid & 15, ks = tid >> 4;

    float wreg[80];
    {
        const float* Wp = g_W2d + (c << 4) + gl;
        #pragma unroll
        for (int kk = 0; kk < 80; kk++) wreg[kk] = Wp[(size_t)(k0 + kk) * NG];
    }
    for (int i = tid; i < 512*4; i += 256)
        wqs[i] = Wq[(size_t)(i >> 2)*NH + n0 + (i & 3)];
    for (int i = tid; i < 1024*4; i += 256)
        was[i] = Wa[(size_t)(i >> 2)*NH + n0 + (i & 3)];
    int g2r = tid >> 4;
    float bv = bias[(g2r & 3)*NH + (c << 2) + (g2r >> 2)];
    __syncthreads();

    unsigned idx = 0;
    for (int t = 0; t < NTD; t++) {
        const float* h_in  = g_h[t & 1];
        const float* c_in  = g_c[t & 1];
        float* h_out = g_h[(t + 1) & 1];
        float* c_out = g_c[(t + 1) & 1];

        // ===== phase 1: LSTM =====
        #pragma unroll
        for (int b = 0; b < 16; b++)
            for (int k = tid; k < 1280; k += 256) {
                float v;
                if (k < NE)           v = g_remb[(b*NTD + t)*NE + k];
                else if (k < NE + NH) v = __ldcg(&g_attn[b*NH + (k - NE)]);
                else                  v = __ldcg(&h_in[b*NH + (k - NE - NH)]);
                xs[k*PX + b] = v;
            }
        __syncthreads();
        {
            u64 acc[8];
            #pragma unroll
            for (int p = 0; p < 8; p++) acc[p] = 0ULL;
            #pragma unroll
            for (int kk = 0; kk < 80; kk++) {
                u64 w2 = packdup(wreg[kk]);
                const u64* xk = (const u64*)(xs + (k0 + kk)*PX);
                #pragma unroll
                for (int p = 0; p < 8; p++) fma2(acc[p], xk[p], w2);
            }
            #pragma unroll
            for (int p = 0; p < 8; p++) {
                float lo, hi; unpack2(acc[p], lo, hi);
                zp[tid*PX + 2*p]   = lo;
                zp[tid*PX + 2*p+1] = hi;
            }
        }
        __syncthreads();
        {
            int g2 = tid >> 4, b = tid & 15;
            float sum = 0.f;
            #pragma unroll
            for (int ss = 0; ss < 16; ss++) sum += zp[(g2 + 16*ss)*PX + b];
            zz[g2*16 + b] = sum + bv;
        }
        __syncthreads();
        if (tid < 64) {
            int jl = tid >> 4, b = tid & 15;
            int jg = (c << 2) + jl;
            float iv = zz[(jl*4 + 0)*16 + b];
            float jv = zz[(jl*4 + 1)*16 + b];
            float fv = zz[(jl*4 + 2)*16 + b];
            float ov = zz[(jl*4 + 3)*16 + b];
            float cold = c_in[b*NH + jg];
            float c2 = cold * sigf(fv + 1.f) + sigf(iv) * tanhf(jv);
            float h2 = tanhf(c2) * sigf(ov);
            h_out[b*NH + jg] = h2;
            c_out[b*NH + jg] = c2;
        }
        idx++; gbar2(g_cntD, &g_epochD, c, idx);

        // ===== phase 2: pq = h2 @ Wq (4 n-cols per CTA) =====
        {
            const float4* wq4 = (const float4*)wqs;
            const float* hp = h_out + bq*NH + ks*32;
            float a0 = 0.f, a1 = 0.f, a2 = 0.f, a3 = 0.f;
            #pragma unroll
            for (int kk = 0; kk < 32; kk++) {
                float x = __ldcg(hp + kk);
                float4 w = wq4[ks*32 + kk];
                a0 = fmaf(x, w.x, a0);
                a1 = fmaf(x, w.y, a1);
                a2 = fmaf(x, w.z, a2);
                a3 = fmaf(x, w.w, a3);
            }
            zp[tid*PX + 0] = a0; zp[tid*PX + 1] = a1;
            zp[tid*PX + 2] = a2; zp[tid*PX + 3] = a3;
        }
        __syncthreads();
        if (tid < 64) {
            int bb = tid >> 2, j = tid & 3;
            float sv = 0.f;
            #pragma unroll
            for (int ss = 0; ss < 16; ss++) sv += zp[(bb + 16*ss)*PX + j];
            g_pq[bb*NH + n0 + j] = sv;
        }
        idx++; gbar2(g_cntD, &g_epochD, c, idx);

        // ===== phase 3: scores + softmax + ctx (CTAs 0..15) =====
        if (c < 16) {
            int b = c;
            for (int i = tid; i < NH; i += 256) { pqv[i] = __ldcg(&g_pq[b*NH + i]); vsv[i] = vatt[i]; }
            __syncthreads();
            int w = tid >> 5, l = tid & 31;
            int len = elen[b];
            for (int te = w; te < NTE; te += 8) {
                const float* kp = g_keys + ((size_t)b*NTE + te)*NH;
                float p = 0.f;
                for (int h = l; h < NH; h += 32)
                    p += vsv[h] * tanhf(kp[h] + pqv[h]);
                #pragma unroll
                for (int off = 16; off > 0; off >>= 1) p += __shfl_xor_sync(0xffffffffu, p, off);
                if (l == 0) scv[te] = (te < len) ? p : NEGV;
            }
            __syncthreads();
            if (tid < 32) {
                float a = scv[tid], b2 = scv[tid + 32];
                float m = fmaxf(a, b2);
                #pragma unroll
                for (int off = 16; off > 0; off >>= 1) m = fmaxf(m, __shfl_xor_sync(0xffffffffu, m, off));
                float e1 = expf(a - m), e2 = expf(b2 - m);
                float ssum = e1 + e2;
                #pragma unroll
                for (int off = 16; off > 0; off >>= 1) ssum += __shfl_xor_sync(0xffffffffu, ssum, off);
                float inv = 1.f / ssum;
                scv[tid] = e1 * inv; scv[tid + 32] = e2 * inv;
            }
            __syncthreads();
            for (int h = tid; h < NH; h += 256) {
                float acc = 0.f;
                const float* ep = g_encout + (size_t)b*NTE*NH + h;
                #pragma unroll 8
                for (int te = 0; te < NTE; te++)
                    acc = fmaf(scv[te], ep[(size_t)te*NH], acc);
                g_ctx[b*NH + h] = acc;
            }
        }
        idx++; gbar2(g_cntD, &g_epochD, c, idx);

        // ===== phase 4: attn2 = [h2|ctx] @ Wa, write attn + bf16 A =====
        {
            const float4* wa4 = (const float4*)was;
            const float* src = (ks < 8) ? (h_out + bq*NH + ks*64)
                                        : (g_ctx + bq*NH + (ks - 8)*64);
            float a0 = 0.f, a1 = 0.f, a2 = 0.f, a3 = 0.f;
            #pragma unroll
            for (int kk = 0; kk < 64; kk++) {
                float x = __ldcg(src + kk);
                float4 w = wa4[ks*64 + kk];
                a0 = fmaf(x, w.x, a0);
                a1 = fmaf(x, w.y, a1);
                a2 = fmaf(x, w.z, a2);
                a3 = fmaf(x, w.w, a3);
            }
            zp[tid*PX + 0] = a0; zp[tid*PX + 1] = a1;
            zp[tid*PX + 2] = a2; zp[tid*PX + 3] = a3;
        }
        __syncthreads();
        if (tid < 64) {
            int bb = tid >> 2, j = tid & 3;
            float sv = 0.f;
            #pragma unroll
            for (int ss = 0; ss < 16; ss++) sv += zp[(bb + 16*ss)*PX + j];
            g_attn[bb*NH + n0 + j] = sv;
            int m = g_rowpos[bb*NTD + t];
            if (m >= 0) {
                __nv_bfloat16 hi = __float2bfloat16(sv);
                g_Ahi[m*NH + n0 + j] = hi;
                g_Alo[m*NH + n0 + j] = __float2bfloat16(sv - __bfloat162float(hi));
            }
        }
        idx++; gbar2(g_cntD, &g_epochD, c, idx);
    }
}

// ---------------- HMMA projection (round-6 proven) ----------------
#define PR_LDA 72
#define PROJ_SMEM (4*128*PR_LDA*2)

__device__ __forceinline__ void ldmA(uint32_t* a, uint32_t addr) {
    asm volatile("ldmatrix.sync.aligned.m8n8.x4.shared.b16 {%0,%1,%2,%3}, [%4];"
                 : "=r"(a[0]), "=r"(a[1]), "=r"(a[2]), "=r"(a[3]) : "r"(addr));
}
__device__ __forceinline__ void ldmB(uint32_t* b, uint32_t addr) {
    asm volatile("ldmatrix.sync.aligned.m8n8.x2.shared.b16 {%0,%1}, [%2];"
                 : "=r"(b[0]), "=r"(b[1]) : "r"(addr));
}
__device__ __forceinline__ void mma16816(float* c, const uint32_t* a, const uint32_t* b) {
    asm volatile("mma.sync.aligned.m16n8k16.row.col.f32.bf16.bf16.f32 "
                 "{%0,%1,%2,%3}, {%4,%5,%6,%7}, {%8,%9}, {%0,%1,%2,%3};"
                 : "+f"(c[0]), "+f"(c[1]), "+f"(c[2]), "+f"(c[3])
                 : "r"(a[0]), "r"(a[1]), "r"(a[2]), "r"(a[3]), "r"(b[0]), "r"(b[1]));
}

__global__ void __launch_bounds__(256, 1)
proj_hmma(float* __restrict__ out)
{
    extern __shared__ __nv_bfloat16 smb[];
    __nv_bfloat16* sAhi = smb;
    __nv_bfloat16* sAlo = smb + 128*PR_LDA;
    __nv_bfloat16* sBhi = smb + 2*128*PR_LDA;
    __nv_bfloat16* sBlo = smb + 3*128*PR_LDA;

    int m0 = blockIdx.x * 128;
    int n0 = blockIdx.y * 128;
    int nr = g_nrows;
    if (m0 >= nr) return;

    int tid = threadIdx.x;
    int wid = tid >> 5, lane = tid & 31;
    int m0w = (wid >> 2) * 64;
    int n0w = (wid & 3) * 32;

    uint32_t sb = smem_u32(smb);
    uint32_t aAhi = sb, aAlo = sb + 128*PR_LDA*2, aBhi = sb + 2*128*PR_LDA*2, aBlo = sb + 3*128*PR_LDA*2;

    float c[4][4][4];
    #pragma unroll
    for (int i = 0; i < 4; i++)
        #pragma unroll
        for (int j = 0; j < 4; j++)
            #pragma unroll
            for (int q = 0; q < 4; q++) c[i][j][q] = 0.f;

    for (int ch = 0; ch < 8; ch++) {
        int k0 = ch * 64;
        for (int i = tid; i < 1024; i += 256) {
            int m = i >> 3, kb = i & 7;
            size_t go = (size_t)(m0 + m)*NH + k0 + kb*8;
            int so = m*PR_LDA + kb*8;
            *(uint4*)&sAhi[so] = *(const uint4*)&g_Ahi[go];
            *(uint4*)&sAlo[so] = *(const uint4*)&g_Alo[go];
        }
        for (int i = tid; i < 1024; i += 256) {
            int n = i >> 3, kb = i & 7;
            size_t go = (size_t)(n0 + n)*NH + k0 + kb*8;
            int so = n*PR_LDA + kb*8;
            *(uint4*)&sBhi[so] = *(const uint4*)&g_Wphi[go];
            *(uint4*)&sBlo[so] = *(const uint4*)&g_Wplo[go];
        }
        __syncthreads();

        #pragma unroll
        for (int ksp = 0; ksp < 4; ksp++) {
            int kp = ksp * 16;
            uint32_t ahi[4][4], alo[4][4], bhi[4][2], blo[4][2];
            #pragma unroll
            for (int mt = 0; mt < 4; mt++) {
                uint32_t off = ((m0w + mt*16 + (lane & 15)) * PR_LDA + kp + ((lane >> 4) << 3)) * 2;
                ldmA(ahi[mt], aAhi + off);
                ldmA(alo[mt], aAlo + off);
            }
            #pragma unroll
            for (int nt = 0; nt < 4; nt++) {
                uint32_t off = ((n0w + nt*8 + (lane & 7)) * PR_LDA + kp + (((lane >> 3) & 1) << 3)) * 2;
                ldmB(bhi[nt], aBhi + off);
                ldmB(blo[nt], aBlo + off);
            }
            #pragma unroll
            for (int mt = 0; mt < 4; mt++)
                #pragma unroll
                for (int nt = 0; nt < 4; nt++) {
                    mma16816(c[mt][nt], ahi[mt], bhi[nt]);
                    mma16816(c[mt][nt], ahi[mt], blo[nt]);
                    mma16816(c[mt][nt], alo[mt], bhi[nt]);
                }
        }
        __syncthreads();
    }

    int rg = lane >> 2, cg = (lane & 3) * 2;
    #pragma unroll
    for (int mt = 0; mt < 4; mt++) {
        #pragma unroll
        for (int half = 0; half < 2; half++) {
            int mloc = m0w + mt*16 + rg + half*8;
            int m = m0 + mloc;
            if (m < nr) {
                int orow = g_outrow[m];
                float* obase = out + (size_t)orow*NV;
                #pragma unroll
                for (int nt = 0; nt < 4; nt++) {
                    int nn = n0 + n0w + nt*8 + cg;
                    float v0 = c[mt][nt][half*2 + 0];
                    float v1 = c[mt][nt][half*2 + 1];
                    if (nn + 1 < NV) {
                        *(float2*)(obase + nn) = make_float2(v0, v1);
                    } else if (nn < NV) {
                        obase[nn] = v0;
                    }
                }
            }
        }
    }
}

// ---------------- launch ----------------
extern "C" void kernel_launch(void* const* d_in, const int* in_sizes, int n_in,
                              void* d_out, int out_size)
{
    const int*   enc_in  = (const int*)d_in[0];
    const int*   dec_in  = (const int*)d_in[1];
    const int*   elen    = (const int*)d_in[2];
    const int*   dlen    = (const int*)d_in[3];
    const float* emb     = (const float*)d_in[4];
    const float* W_enc   = (const float*)d_in[5];
    const float* b_enc   = (const float*)d_in[6];
    const float* W_dec   = (const float*)d_in[7];
    const float* b_dec   = (const float*)d_in[8];
    const float* W_mem   = (const float*)d_in[9];
    const float* W_query = (const float*)d_in[10];
    const float* v_att   = (const float*)d_in[11];
    const float* W_attn  = (const float*)d_in[12];
    const float* W_proj  = (const float*)d_in[13];
    float* out = (float*)d_out;

    const int smemE = (768*PX + 256*PX + 256) * 4;                   //  74,752 B
    const int smemD = (1280*PX + 256*PX + 256 + 2048 + 4096) * 4;    // 136,192 B
    const int smemK = (2*16*(NH + 4)) * 4;                           //  66,048 B

    cudaFuncSetAttribute(enc_mega,    cudaFuncAttributeMaxDynamicSharedMemorySize, smemE);
    cudaFuncSetAttribute(dec_mega,    cudaFuncAttributeMaxDynamicSharedMemorySize, smemD);
    cudaFuncSetAttribute(keys_kernel, cudaFuncAttributeMaxDynamicSharedMemorySize, smemK);
    cudaFuncSetAttribute(proj_hmma,   cudaFuncAttributeMaxDynamicSharedMemorySize, PROJ_SMEM);

    prep_kernel<<<256, 256>>>(enc_in, dec_in, dlen, emb);
    permW_kernel<<<512, 256>>>(W_enc, W_dec);
    zero_kernel<<<1024, 256>>>((float4*)out, NB*NTD*NV/4);
    wconv_kernel<<<dim3(NVP/64, NH/64), 256>>>(W_proj);

    enc_mega<<<128, 256, smemE>>>(b_enc, elen);
    keys_kernel<<<dim3(32, 64), 256, smemK>>>(W_mem);
    dec_mega<<<128, 256, smemD>>>(b_dec, W_query, v_att, W_attn, elen);

    proj_hmma<<<dim3(4, 704), 256, PROJ_SMEM>>>(out);
}

// round 9
// speedup vs baseline: 1.1575x; 1.1575x over previous
#include <cuda_runtime.h>
#include <cuda_bf16.h>
#include <math.h>
#include <stdint.h>

#define NB 16
#define NTE 64
#define NTD 32
#define NE 256
#define NH 512
#define NG 2048
#define NV 90000
#define NVP 90112
#define NEGV (-1e9f)
#define PX 18

typedef unsigned long long u64;

// ---------------- device scratch ----------------
__device__ float g_qemb[NB*NTE*NE];
__device__ float g_remb[NB*NTD*NE];
__device__ float g_h[2][NB*NH];
__device__ float g_c[2][NB*NH];
__device__ float g_attn[NB*NH];
__device__ float g_encout[NB*NTE*NH];
__device__ float g_keys[NB*NTE*NH];
__device__ float g_pq[NB*NH];
__device__ float g_ctx[NB*NH];
__device__ float g_score[NB*NTE];
__device__ int   g_outrow[NB*NTD];
__device__ int   g_rowpos[NB*NTD];
__device__ int   g_nrows;
__device__ float g_W2e[768*NG];
__device__ float g_W2d[1280*NG];
// all-read-all barrier flags: one 256B line per CTA
__device__ unsigned g_flagsE[128*64];
__device__ unsigned g_flagsD[128*64];
__device__ __nv_bfloat16 g_Wphi[(size_t)NVP*NH];
__device__ __nv_bfloat16 g_Wplo[(size_t)NVP*NH];
__device__ __nv_bfloat16 g_Ahi[512*NH];
__device__ __nv_bfloat16 g_Alo[512*NH];

// ---------------- fast math (abs err ~1e-7, inputs bounded) ----------------
__device__ __forceinline__ float fsig(float x) {
    return __fdividef(1.f, 1.f + __expf(-x));
}
__device__ __forceinline__ float ftanh(float x) {
    x = fminf(fmaxf(x, -15.f), 15.f);
    float a = __expf(2.f * x);
    return __fdividef(a - 1.f, a + 1.f);
}

__device__ __forceinline__ u64 packdup(float v) {
    u64 r;
    asm("mov.b64 %0, {%1, %1};" : "=l"(r) : "r"(__float_as_uint(v)));
    return r;
}
__device__ __forceinline__ void fma2(u64& d, u64 a, u64 b) {
    asm("fma.rn.f32x2 %0, %1, %2, %0;" : "+l"(d) : "l"(a), "l"(b));
}
__device__ __forceinline__ void unpack2(u64 v, float& lo, float& hi) {
    unsigned l, h;
    asm("mov.b64 {%0, %1}, %2;" : "=r"(l), "=r"(h) : "l"(v));
    lo = __uint_as_float(l); hi = __uint_as_float(h);
}
__device__ __forceinline__ uint32_t smem_u32(const void* p) {
    uint32_t a;
    asm("{ .reg .u64 t; cvta.to.shared.u64 t, %1; cvt.u32.u64 %0, t; }" : "=r"(a) : "l"(p));
    return a;
}

// ---------------- all-read-all grid barrier ----------------
// Each CTA release-stores epoch to its own 256B-spaced flag (no atomics).
// Warp 0 of each CTA polls all 128 flags (4 independent loads/lane).
__device__ __forceinline__ void gbar3(unsigned* flags, int c, unsigned epoch) {
    __syncthreads();
    if (threadIdx.x == 0) {
        asm volatile("st.release.gpu.global.u32 [%0], %1;"
                     :: "l"(flags + (c << 6)), "r"(epoch) : "memory");
    }
    if (threadIdx.x < 32) {
        int lane = threadIdx.x;
        unsigned* p0 = flags + ((lane*4 + 0) << 6);
        unsigned* p1 = flags + ((lane*4 + 1) << 6);
        unsigned* p2 = flags + ((lane*4 + 2) << 6);
        unsigned* p3 = flags + ((lane*4 + 3) << 6);
        for (;;) {
            unsigned v0, v1, v2, v3;
            asm volatile("ld.acquire.gpu.global.u32 %0, [%1];" : "=r"(v0) : "l"(p0) : "memory");
            asm volatile("ld.acquire.gpu.global.u32 %0, [%1];" : "=r"(v1) : "l"(p1) : "memory");
            asm volatile("ld.acquire.gpu.global.u32 %0, [%1];" : "=r"(v2) : "l"(p2) : "memory");
            asm volatile("ld.acquire.gpu.global.u32 %0, [%1];" : "=r"(v3) : "l"(p3) : "memory");
            unsigned mn = min(min(v0, v1), min(v2, v3));
            if (mn >= epoch) break;
        }
    }
    __syncthreads();
}

// ---------------- prep ----------------
__global__ void prep_kernel(const int* __restrict__ enc_in, const int* __restrict__ dec_in,
                            const int* __restrict__ dlen, const float* __restrict__ emb)
{
    int idx = blockIdx.x * blockDim.x + threadIdx.x;
    int stride = gridDim.x * blockDim.x;
    for (int i = idx; i < NB*NTE*NE; i += stride) {
        int e = i & (NE - 1); int bt = i >> 8;
        g_qemb[i] = emb[(size_t)enc_in[bt] * NE + e];
    }
    for (int i = idx; i < NB*NTD*NE; i += stride) {
        int e = i & (NE - 1); int bt = i >> 8;
        g_remb[i] = emb[(size_t)dec_in[bt] * NE + e];
    }
    for (int i = idx; i < NB*NH; i += stride) {
        g_h[0][i] = 0.f; g_c[0][i] = 0.f; g_attn[i] = 0.f;
    }
    __nv_bfloat16 z = __float2bfloat16(0.f);
    for (int i = idx; i < 512*NH; i += stride) { g_Ahi[i] = z; g_Alo[i] = z; }
    for (int i = idx; i < 128*64; i += stride) { g_flagsE[i] = 0u; g_flagsD[i] = 0u; }
    if (idx == 0) {
        int n = 0;
        for (int b = 0; b < NB; b++) {
            int L = dlen[b]; if (L > NTD) L = NTD; if (L < 0) L = 0;
            for (int t2 = 0; t2 < NTD; t2++) {
                if (t2 < L) { g_outrow[n] = b*NTD + t2; g_rowpos[b*NTD + t2] = n; n++; }
                else g_rowpos[b*NTD + t2] = -1;
            }
        }
        g_nrows = n;
    }
}

// ---------------- permute LSTM weights ----------------
__global__ void permW_kernel(const float* __restrict__ We, const float* __restrict__ Wd)
{
    int idx = blockIdx.x * blockDim.x + threadIdx.x;
    int stride = gridDim.x * blockDim.x;
    for (int i = idx; i < 768*NG; i += stride) {
        int k = i >> 11, g2 = i & (NG - 1);
        int blk = g2 >> 4, x = g2 & 15, jl = x >> 2, q = x & 3;
        g_W2e[i] = We[(size_t)k*NG + q*NH + (blk << 2) + jl];
    }
    for (int i = idx; i < 1280*NG; i += stride) {
        int k = i >> 11, g2 = i & (NG - 1);
        int blk = g2 >> 4, x = g2 & 15, jl = x >> 2, q = x & 3;
        g_W2d[i] = Wd[(size_t)k*NG + q*NH + (blk << 2) + jl];
    }
}

__global__ void zero_kernel(float4* __restrict__ out, int n4)
{
    int idx = blockIdx.x * blockDim.x + threadIdx.x;
    int stride = gridDim.x * blockDim.x;
    float4 z = make_float4(0.f, 0.f, 0.f, 0.f);
    for (int i = idx; i < n4; i += stride) out[i] = z;
}

// ---------------- W_proj -> transposed bf16 hi/lo ----------------
__global__ void wconv_kernel(const float* __restrict__ Wp)
{
    __shared__ float tile[64][65];
    int v0 = blockIdx.x * 64, k0 = blockIdx.y * 64;
    int tid = threadIdx.x;
    for (int i = tid; i < 4096; i += 256) {
        int kk = i >> 6, vv = i & 63;
        int v = v0 + vv;
        tile[kk][vv] = (v < NV) ? Wp[(size_t)(k0 + kk)*NV + v] : 0.f;
    }
    __syncthreads();
    for (int i = tid; i < 4096; i += 256) {
        int vv = i >> 6, kk = i & 63;
        float x = tile[kk][vv];
        __nv_bfloat16 hi = __float2bfloat16(x);
        float r = x - __bfloat162float(hi);
        size_t o = (size_t)(v0 + vv)*NH + k0 + kk;
        g_Wphi[o] = hi;
        g_Wplo[o] = __float2bfloat16(r);
    }
}

// ---------------- persistent encoder ----------------
__global__ void __launch_bounds__(256, 1)
enc_mega(const float* __restrict__ bias, const int* __restrict__ elen)
{
    extern __shared__ float sm[];
    float* xs = sm;                 // [768][PX]
    float* zp = sm + 768*PX;        // [256][PX]
    float* zz = zp + 256*PX;        // [256]

    int tid = threadIdx.x;
    int c = blockIdx.x;
    int gl = tid & 15, s = tid >> 4;
    int k0 = s * 48;

    float wreg[48];
    {
        const float* Wp = g_W2e + (c << 4) + gl;
        #pragma unroll
        for (int kk = 0; kk < 48; kk++) wreg[kk] = Wp[(size_t)(k0 + kk) * NG];
    }
    int g2r = tid >> 4;
    float bv = bias[(g2r & 3)*NH + (c << 2) + (g2r >> 2)];

    for (int t = 0; t < NTE; t++) {
        const float* h_in  = g_h[t & 1];
        const float* c_in  = g_c[t & 1];
        float* h_out = g_h[(t + 1) & 1];
        float* c_out = g_c[(t + 1) & 1];

        #pragma unroll
        for (int b = 0; b < 16; b++)
            for (int k = tid; k < 768; k += 256) {
                float v = (k < NE) ? g_qemb[(b*NTE + t)*NE + k]
                                   : __ldcg(&h_in[b*NH + (k - NE)]);
                xs[k*PX + b] = v;
            }
        __syncthreads();

        u64 acc[8];
        #pragma unroll
        for (int p = 0; p < 8; p++) acc[p] = 0ULL;
        #pragma unroll
        for (int kk = 0; kk < 48; kk++) {
            u64 w2 = packdup(wreg[kk]);
            const u64* xk = (const u64*)(xs + (k0 + kk)*PX);
            #pragma unroll
            for (int p = 0; p < 8; p++) fma2(acc[p], xk[p], w2);
        }
        #pragma unroll
        for (int p = 0; p < 8; p++) {
            float lo, hi; unpack2(acc[p], lo, hi);
            zp[tid*PX + 2*p]   = lo;
            zp[tid*PX + 2*p+1] = hi;
        }
        __syncthreads();

        {
            int g2 = tid >> 4, b = tid & 15;
            float sum = 0.f;
            #pragma unroll
            for (int ss = 0; ss < 16; ss++) sum += zp[(g2 + 16*ss)*PX + b];
            zz[g2*16 + b] = sum + bv;
        }
        __syncthreads();

        if (tid < 64) {
            int jl = tid >> 4, b = tid & 15;
            int jg = (c << 2) + jl;
            float iv = zz[(jl*4 + 0)*16 + b];
            float jv = zz[(jl*4 + 1)*16 + b];
            float fv = zz[(jl*4 + 2)*16 + b];
            float ov = zz[(jl*4 + 3)*16 + b];
            float cold = c_in[b*NH + jg];
            float c2 = cold * fsig(fv + 1.f) + fsig(iv) * ftanh(jv);
            float h2 = ftanh(c2) * fsig(ov);
            bool valid = t < elen[b];
            float hold = xs[(NE + jg)*PX + b];
            h_out[b*NH + jg] = valid ? h2 : hold;
            c_out[b*NH + jg] = valid ? c2 : cold;
            g_encout[((size_t)b*NTE + t)*NH + jg] = valid ? h2 : 0.f;
        }
        gbar3(g_flagsE, c, (unsigned)(t + 1));
    }
}

// ---------------- keys = enc_out @ W_mem ----------------
__global__ void keys_kernel(const float* __restrict__ Wm)
{
    extern __shared__ float sm[];
    const int KX = NH, KP = NH + 4;
    float* xs = sm;
    float* ws = sm + 16*KP;
    int tid = threadIdx.x;
    int cn = blockIdx.x;
    int cr = blockIdx.y;

    for (int i = tid; i < 16*KX; i += 256) {
        int rl = i >> 9, k = i & 511;
        xs[rl*KP + k] = g_encout[(cr*16 + rl)*NH + k];
    }
    for (int i = tid; i < 16*KX; i += 256) {
        int k = i >> 4, nl = i & 15;
        ws[nl*KP + k] = Wm[k*NH + cn*16 + nl];
    }
    __syncthreads();

    int nl = tid & 15, rl = tid >> 4;
    float a0 = 0.f, a1 = 0.f, a2 = 0.f, a3 = 0.f;
    const float* xp = xs + rl*KP;
    const float* wp = ws + nl*KP;
    #pragma unroll 8
    for (int k = 0; k < KX; k += 4) {
        float4 a = *(const float4*)(xp + k);
        float4 w = *(const float4*)(wp + k);
        a0 = fmaf(a.x, w.x, a0);
        a1 = fmaf(a.y, w.y, a1);
        a2 = fmaf(a.z, w.z, a2);
        a3 = fmaf(a.w, w.w, a3);
    }
    g_keys[(cr*16 + rl)*NH + cn*16 + nl] = (a0 + a1) + (a2 + a3);
}

// ---------------- persistent decoder: 5 phases/step ----------------
// P1 LSTM (128 CTAs) | P2 pq (128, 4 cols) | P3 scores (128: b x te-chunk)
// P4 softmax+ctx (16) | P5 attn2 (128, 4 cols) + bf16 A
__global__ void __launch_bounds__(256, 1)
dec_mega(const float* __restrict__ bias, const float* __restrict__ Wq,
         const float* __restrict__ vatt, const float* __restrict__ Wa,
         const int* __restrict__ elen)
{
    extern __shared__ float sm[];
    float* xs  = sm;                    // [1280][PX]
    float* zp  = sm + 1280*PX;          // [256][PX]
    float* zz  = zp + 256*PX;           // [256]
    float* wqs = zz + 256;              // [512][4]
    float* was = wqs + 2048;            // [1024][4]
    float* pqv = sm;                    // P3/P4 aliases (inside xs)
    float* vsv = sm + 512;
    float* scv = sm + 1024;

    int tid = threadIdx.x;
    int c = blockIdx.x;
    int gl = tid & 15, s = tid >> 4;
    int k0 = s * 80;
    int n0 = c * 4;
    int bq = tid & 15, ks = tid >> 4;

    float wreg[80];
    {
        const float* Wp = g_W2d + (c << 4) + gl;
        #pragma unroll
        for (int kk = 0; kk < 80; kk++) wreg[kk] = Wp[(size_t)(k0 + kk) * NG];
    }
    for (int i = tid; i < 512*4; i += 256)
        wqs[i] = Wq[(size_t)(i >> 2)*NH + n0 + (i & 3)];
    for (int i = tid; i < 1024*4; i += 256)
        was[i] = Wa[(size_t)(i >> 2)*NH + n0 + (i & 3)];
    int g2r = tid >> 4;
    float bv = bias[(g2r & 3)*NH + (c << 2) + (g2r >> 2)];
    __syncthreads();

    unsigned idx = 0;
    for (int t = 0; t < NTD; t++) {
        const float* h_in  = g_h[t & 1];
        const float* c_in  = g_c[t & 1];
        float* h_out = g_h[(t + 1) & 1];
        float* c_out = g_c[(t + 1) & 1];

        // ===== P1: LSTM =====
        #pragma unroll
        for (int b = 0; b < 16; b++)
            for (int k = tid; k < 1280; k += 256) {
                float v;
                if (k < NE)           v = g_remb[(b*NTD + t)*NE + k];
                else if (k < NE + NH) v = __ldcg(&g_attn[b*NH + (k - NE)]);
                else                  v = __ldcg(&h_in[b*NH + (k - NE - NH)]);
                xs[k*PX + b] = v;
            }
        __syncthreads();
        {
            u64 acc[8];
            #pragma unroll
            for (int p = 0; p < 8; p++) acc[p] = 0ULL;
            #pragma unroll
            for (int kk = 0; kk < 80; kk++) {
                u64 w2 = packdup(wreg[kk]);
                const u64* xk = (const u64*)(xs + (k0 + kk)*PX);
                #pragma unroll
                for (int p = 0; p < 8; p++) fma2(acc[p], xk[p], w2);
            }
            #pragma unroll
            for (int p = 0; p < 8; p++) {
                float lo, hi; unpack2(acc[p], lo, hi);
                zp[tid*PX + 2*p]   = lo;
                zp[tid*PX + 2*p+1] = hi;
            }
        }
        __syncthreads();
        {
            int g2 = tid >> 4, b = tid & 15;
            float sum = 0.f;
            #pragma unroll
            for (int ss = 0; ss < 16; ss++) sum += zp[(g2 + 16*ss)*PX + b];
            zz[g2*16 + b] = sum + bv;
        }
        __syncthreads();
        if (tid < 64) {
            int jl = tid >> 4, b = tid & 15;
            int jg = (c << 2) + jl;
            float iv = zz[(jl*4 + 0)*16 + b];
            float jv = zz[(jl*4 + 1)*16 + b];
            float fv = zz[(jl*4 + 2)*16 + b];
            float ov = zz[(jl*4 + 3)*16 + b];
            float cold = c_in[b*NH + jg];
            float c2 = cold * fsig(fv + 1.f) + fsig(iv) * ftanh(jv);
            float h2 = ftanh(c2) * fsig(ov);
            h_out[b*NH + jg] = h2;
            c_out[b*NH + jg] = c2;
        }
        idx++; gbar3(g_flagsD, c, idx);

        // ===== P2: pq = h2 @ Wq (4 n-cols per CTA) =====
        {
            const float4* wq4 = (const float4*)wqs;
            const float* hp = h_out + bq*NH + ks*32;
            float a0 = 0.f, a1 = 0.f, a2 = 0.f, a3 = 0.f;
            #pragma unroll
            for (int kk = 0; kk < 32; kk++) {
                float x = __ldcg(hp + kk);
                float4 w = wq4[ks*32 + kk];
                a0 = fmaf(x, w.x, a0);
                a1 = fmaf(x, w.y, a1);
                a2 = fmaf(x, w.z, a2);
                a3 = fmaf(x, w.w, a3);
            }
            zp[tid*PX + 0] = a0; zp[tid*PX + 1] = a1;
            zp[tid*PX + 2] = a2; zp[tid*PX + 3] = a3;
        }
        __syncthreads();
        if (tid < 64) {
            int bb = tid >> 2, j = tid & 3;
            float sv = 0.f;
            #pragma unroll
            for (int ss = 0; ss < 16; ss++) sv += zp[(bb + 16*ss)*PX + j];
            g_pq[bb*NH + n0 + j] = sv;
        }
        idx++; gbar3(g_flagsD, c, idx);

        // ===== P3: scores (128 CTAs: b = c&15, te-chunk = c>>4) =====
        {
            int b = c & 15, chunk = c >> 4;
            for (int i = tid; i < NH; i += 256) {
                pqv[i] = __ldcg(&g_pq[b*NH + i]);
                vsv[i] = vatt[i];
            }
            __syncthreads();
            int w = tid >> 5, l = tid & 31;
            int te = chunk*8 + w;
            const float* kp = g_keys + ((size_t)b*NTE + te)*NH;
            float p = 0.f;
            #pragma unroll 4
            for (int h = l; h < NH; h += 32)
                p += vsv[h] * ftanh(kp[h] + pqv[h]);
            #pragma unroll
            for (int off = 16; off > 0; off >>= 1) p += __shfl_xor_sync(0xffffffffu, p, off);
            if (l == 0) {
                int len = elen[b];
                g_score[b*NTE + te] = (te < len) ? p : NEGV;
            }
        }
        idx++; gbar3(g_flagsD, c, idx);

        // ===== P4: softmax + ctx (CTAs 0..15) =====
        if (c < 16) {
            int b = c;
            if (tid < 64) scv[tid] = __ldcg(&g_score[b*NTE + tid]);
            __syncthreads();
            if (tid < 32) {
                float a = scv[tid], b2 = scv[tid + 32];
                float m = fmaxf(a, b2);
                #pragma unroll
                for (int off = 16; off > 0; off >>= 1) m = fmaxf(m, __shfl_xor_sync(0xffffffffu, m, off));
                float e1 = __expf(a - m), e2 = __expf(b2 - m);
                float ssum = e1 + e2;
                #pragma unroll
                for (int off = 16; off > 0; off >>= 1) ssum += __shfl_xor_sync(0xffffffffu, ssum, off);
                float inv = __fdividef(1.f, ssum);
                scv[tid] = e1 * inv; scv[tid + 32] = e2 * inv;
            }
            __syncthreads();
            for (int h = tid; h < NH; h += 256) {
                float acc = 0.f;
                const float* ep = g_encout + (size_t)b*NTE*NH + h;
                #pragma unroll 8
                for (int te = 0; te < NTE; te++)
                    acc = fmaf(scv[te], ep[(size_t)te*NH], acc);
                g_ctx[b*NH + h] = acc;
            }
        }
        idx++; gbar3(g_flagsD, c, idx);

        // ===== P5: attn2 = [h2|ctx] @ Wa, write attn + bf16 A =====
        {
            const float4* wa4 = (const float4*)was;
            const float* src = (ks < 8) ? (h_out + bq*NH + ks*64)
                                        : (g_ctx + bq*NH + (ks - 8)*64);
            float a0 = 0.f, a1 = 0.f, a2 = 0.f, a3 = 0.f;
            #pragma unroll
            for (int kk = 0; kk < 64; kk++) {
                float x = __ldcg(src + kk);
                float4 w = wa4[ks*64 + kk];
                a0 = fmaf(x, w.x, a0);
                a1 = fmaf(x, w.y, a1);
                a2 = fmaf(x, w.z, a2);
                a3 = fmaf(x, w.w, a3);
            }
            zp[tid*PX + 0] = a0; zp[tid*PX + 1] = a1;
            zp[tid*PX + 2] = a2; zp[tid*PX + 3] = a3;
        }
        __syncthreads();
        if (tid < 64) {
            int bb = tid >> 2, j = tid & 3;
            float sv = 0.f;
            #pragma unroll
            for (int ss = 0; ss < 16; ss++) sv += zp[(bb + 16*ss)*PX + j];
            g_attn[bb*NH + n0 + j] = sv;
            int m = g_rowpos[bb*NTD + t];
            if (m >= 0) {
                __nv_bfloat16 hi = __float2bfloat16(sv);
                g_Ahi[m*NH + n0 + j] = hi;
                g_Alo[m*NH + n0 + j] = __float2bfloat16(sv - __bfloat162float(hi));
            }
        }
        idx++; gbar3(g_flagsD, c, idx);
    }
}

// ---------------- HMMA projection (proven) ----------------
#define PR_LDA 72
#define PROJ_SMEM (4*128*PR_LDA*2)

__device__ __forceinline__ void ldmA(uint32_t* a, uint32_t addr) {
    asm volatile("ldmatrix.sync.aligned.m8n8.x4.shared.b16 {%0,%1,%2,%3}, [%4];"
                 : "=r"(a[0]), "=r"(a[1]), "=r"(a[2]), "=r"(a[3]) : "r"(addr));
}
__device__ __forceinline__ void ldmB(uint32_t* b, uint32_t addr) {
    asm volatile("ldmatrix.sync.aligned.m8n8.x2.shared.b16 {%0,%1}, [%2];"
                 : "=r"(b[0]), "=r"(b[1]) : "r"(addr));
}
__device__ __forceinline__ void mma16816(float* c, const uint32_t* a, const uint32_t* b) {
    asm volatile("mma.sync.aligned.m16n8k16.row.col.f32.bf16.bf16.f32 "
                 "{%0,%1,%2,%3}, {%4,%5,%6,%7}, {%8,%9}, {%0,%1,%2,%3};"
                 : "+f"(c[0]), "+f"(c[1]), "+f"(c[2]), "+f"(c[3])
                 : "r"(a[0]), "r"(a[1]), "r"(a[2]), "r"(a[3]), "r"(b[0]), "r"(b[1]));
}

__global__ void __launch_bounds__(256, 1)
proj_hmma(float* __restrict__ out)
{
    extern __shared__ __nv_bfloat16 smb[];
    __nv_bfloat16* sAhi = smb;
    __nv_bfloat16* sAlo = smb + 128*PR_LDA;
    __nv_bfloat16* sBhi = smb + 2*128*PR_LDA;
    __nv_bfloat16* sBlo = smb + 3*128*PR_LDA;

    int m0 = blockIdx.x * 128;
    int n0 = blockIdx.y * 128;
    int nr = g_nrows;
    if (m0 >= nr) return;

    int tid = threadIdx.x;
    int wid = tid >> 5, lane = tid & 31;
    int m0w = (wid >> 2) * 64;
    int n0w = (wid & 3) * 32;

    uint32_t sb = smem_u32(smb);
    uint32_t aAhi = sb, aAlo = sb + 128*PR_LDA*2, aBhi = sb + 2*128*PR_LDA*2, aBlo = sb + 3*128*PR_LDA*2;

    float c[4][4][4];
    #pragma unroll
    for (int i = 0; i < 4; i++)
        #pragma unroll
        for (int j = 0; j < 4; j++)
            #pragma unroll
            for (int q = 0; q < 4; q++) c[i][j][q] = 0.f;

    for (int ch = 0; ch < 8; ch++) {
        int k0 = ch * 64;
        for (int i = tid; i < 1024; i += 256) {
            int m = i >> 3, kb = i & 7;
            size_t go = (size_t)(m0 + m)*NH + k0 + kb*8;
            int so = m*PR_LDA + kb*8;
            *(uint4*)&sAhi[so] = *(const uint4*)&g_Ahi[go];
            *(uint4*)&sAlo[so] = *(const uint4*)&g_Alo[go];
        }
        for (int i = tid; i < 1024; i += 256) {
            int n = i >> 3, kb = i & 7;
            size_t go = (size_t)(n0 + n)*NH + k0 + kb*8;
            int so = n*PR_LDA + kb*8;
            *(uint4*)&sBhi[so] = *(const uint4*)&g_Wphi[go];
            *(uint4*)&sBlo[so] = *(const uint4*)&g_Wplo[go];
        }
        __syncthreads();

        #pragma unroll
        for (int ksp = 0; ksp < 4; ksp++) {
            int kp = ksp * 16;
            uint32_t ahi[4][4], alo[4][4], bhi[4][2], blo[4][2];
            #pragma unroll
            for (int mt = 0; mt < 4; mt++) {
                uint32_t off = ((m0w + mt*16 + (lane & 15)) * PR_LDA + kp + ((lane >> 4) << 3)) * 2;
                ldmA(ahi[mt], aAhi + off);
                ldmA(alo[mt], aAlo + off);
            }
            #pragma unroll
            for (int nt = 0; nt < 4; nt++) {
                uint32_t off = ((n0w + nt*8 + (lane & 7)) * PR_LDA + kp + (((lane >> 3) & 1) << 3)) * 2;
                ldmB(bhi[nt], aBhi + off);
                ldmB(blo[nt], aBlo + off);
            }
            #pragma unroll
            for (int mt = 0; mt < 4; mt++)
                #pragma unroll
                for (int nt = 0; nt < 4; nt++) {
                    mma16816(c[mt][nt], ahi[mt], bhi[nt]);
                    mma16816(c[mt][nt], ahi[mt], blo[nt]);
                    mma16816(c[mt][nt], alo[mt], bhi[nt]);
                }
        }
        __syncthreads();
    }

    int rg = lane >> 2, cg = (lane & 3) * 2;
    #pragma unroll
    for (int mt = 0; mt < 4; mt++) {
        #pragma unroll
        for (int half = 0; half < 2; half++) {
            int mloc = m0w + mt*16 + rg + half*8;
            int m = m0 + mloc;
            if (m < nr) {
                int orow = g_outrow[m];
                float* obase = out + (size_t)orow*NV;
                #pragma unroll
                for (int nt = 0; nt < 4; nt++) {
                    int nn = n0 + n0w + nt*8 + cg;
                    float v0 = c[mt][nt][half*2 + 0];
                    float v1 = c[mt][nt][half*2 + 1];
                    if (nn + 1 < NV) {
                        *(float2*)(obase + nn) = make_float2(v0, v1);
                    } else if (nn < NV) {
                        obase[nn] = v0;
                    }
                }
            }
        }
    }
}

// ---------------- launch ----------------
extern "C" void kernel_launch(void* const* d_in, const int* in_sizes, int n_in,
                              void* d_out, int out_size)
{
    const int*   enc_in  = (const int*)d_in[0];
    const int*   dec_in  = (const int*)d_in[1];
    const int*   elen    = (const int*)d_in[2];
    const int*   dlen    = (const int*)d_in[3];
    const float* emb     = (const float*)d_in[4];
    const float* W_enc   = (const float*)d_in[5];
    const float* b_enc   = (const float*)d_in[6];
    const float* W_dec   = (const float*)d_in[7];
    const float* b_dec   = (const float*)d_in[8];
    const float* W_mem   = (const float*)d_in[9];
    const float* W_query = (const float*)d_in[10];
    const float* v_att   = (const float*)d_in[11];
    const float* W_attn  = (const float*)d_in[12];
    const float* W_proj  = (const float*)d_in[13];
    float* out = (float*)d_out;

    const int smemE = (768*PX + 256*PX + 256) * 4;
    const int smemD = (1280*PX + 256*PX + 256 + 2048 + 4096) * 4;
    const int smemK = (2*16*(NH + 4)) * 4;

    cudaFuncSetAttribute(enc_mega,    cudaFuncAttributeMaxDynamicSharedMemorySize, smemE);
    cudaFuncSetAttribute(dec_mega,    cudaFuncAttributeMaxDynamicSharedMemorySize, smemD);
    cudaFuncSetAttribute(keys_kernel, cudaFuncAttributeMaxDynamicSharedMemorySize, smemK);
    cudaFuncSetAttribute(proj_hmma,   cudaFuncAttributeMaxDynamicSharedMemorySize, PROJ_SMEM);

    prep_kernel<<<256, 256>>>(enc_in, dec_in, dlen, emb);
    permW_kernel<<<512, 256>>>(W_enc, W_dec);
    zero_kernel<<<1024, 256>>>((float4*)out, NB*NTD*NV/4);
    wconv_kernel<<<dim3(NVP/64, NH/64), 256>>>(W_proj);

    enc_mega<<<128, 256, smemE>>>(b_enc, elen);
    keys_kernel<<<dim3(32, 64), 256, smemK>>>(W_mem);
    dec_mega<<<128, 256, smemD>>>(b_dec, W_query, v_att, W_attn, elen);

    proj_hmma<<<dim3(4, 704), 256, PROJ_SMEM>>>(out);
}

// round 10
// speedup vs baseline: 1.4048x; 1.2137x over previous
#include <cuda_runtime.h>
#include <cuda_bf16.h>
#include <math.h>
#include <stdint.h>

#define NB 16
#define NTE 64
#define NTD 32
#define NE 256
#define NH 512
#define NG 2048
#define NV 90000
#define NEGV (-1e9f)
#define PX 18

typedef unsigned long long u64;

// ---------------- device scratch ----------------
__device__ float g_qemb[NB*NTE*NE];
__device__ float g_remb[NB*NTD*NE];
__device__ float g_h[2][NB*NH];
__device__ float g_c[2][NB*NH];
__device__ float g_attn[NB*NH];
__device__ float g_encout[NB*NTE*NH];
__device__ float g_keys[NB*NTE*NH];
__device__ float g_pq[NB*NH];
__device__ float g_ctx[NB*NH];
__device__ float g_score[NB*NTE];
__device__ int   g_outrow[NB*NTD];
__device__ int   g_rowpos[NB*NTD];
__device__ int   g_nrows;
__device__ float g_W2e[768*NG];
__device__ float g_W2d[1280*NG];
__device__ unsigned g_flagsE[128*64];
__device__ unsigned g_flagsD[128*64];
__device__ __nv_bfloat16 g_Ahi[512*NH];
__device__ __nv_bfloat16 g_Alo[512*NH];

// ---------------- fast math ----------------
__device__ __forceinline__ float fsig(float x) {
    return __fdividef(1.f, 1.f + __expf(-x));
}
__device__ __forceinline__ float ftanh(float x) {
    x = fminf(fmaxf(x, -15.f), 15.f);
    float a = __expf(2.f * x);
    return __fdividef(a - 1.f, a + 1.f);
}

__device__ __forceinline__ u64 packdup(float v) {
    u64 r;
    asm("mov.b64 %0, {%1, %1};" : "=l"(r) : "r"(__float_as_uint(v)));
    return r;
}
__device__ __forceinline__ void fma2(u64& d, u64 a, u64 b) {
    asm("fma.rn.f32x2 %0, %1, %2, %0;" : "+l"(d) : "l"(a), "l"(b));
}
__device__ __forceinline__ void unpack2(u64 v, float& lo, float& hi) {
    unsigned l, h;
    asm("mov.b64 {%0, %1}, %2;" : "=r"(l), "=r"(h) : "l"(v));
    lo = __uint_as_float(l); hi = __uint_as_float(h);
}
__device__ __forceinline__ uint32_t smem_u32(const void* p) {
    uint32_t a;
    asm("{ .reg .u64 t; cvta.to.shared.u64 t, %1; cvt.u32.u64 %0, t; }" : "=r"(a) : "l"(p));
    return a;
}

// ---------------- all-read-all grid barrier ----------------
__device__ __forceinline__ void gbar3(unsigned* flags, int c, unsigned epoch) {
    __syncthreads();
    if (threadIdx.x == 0) {
        asm volatile("st.release.gpu.global.u32 [%0], %1;"
                     :: "l"(flags + (c << 6)), "r"(epoch) : "memory");
    }
    if (threadIdx.x < 32) {
        int lane = threadIdx.x;
        unsigned* p0 = flags + ((lane*4 + 0) << 6);
        unsigned* p1 = flags + ((lane*4 + 1) << 6);
        unsigned* p2 = flags + ((lane*4 + 2) << 6);
        unsigned* p3 = flags + ((lane*4 + 3) << 6);
        for (;;) {
            unsigned v0, v1, v2, v3;
            asm volatile("ld.acquire.gpu.global.u32 %0, [%1];" : "=r"(v0) : "l"(p0) : "memory");
            asm volatile("ld.acquire.gpu.global.u32 %0, [%1];" : "=r"(v1) : "l"(p1) : "memory");
            asm volatile("ld.acquire.gpu.global.u32 %0, [%1];" : "=r"(v2) : "l"(p2) : "memory");
            asm volatile("ld.acquire.gpu.global.u32 %0, [%1];" : "=r"(v3) : "l"(p3) : "memory");
            unsigned mn = min(min(v0, v1), min(v2, v3));
            if (mn >= epoch) break;
        }
    }
    __syncthreads();
}

// ---------------- prep ----------------
__global__ void prep_kernel(const int* __restrict__ enc_in, const int* __restrict__ dec_in,
                            const int* __restrict__ dlen, const float* __restrict__ emb)
{
    int idx = blockIdx.x * blockDim.x + threadIdx.x;
    int stride = gridDim.x * blockDim.x;
    for (int i = idx; i < NB*NTE*NE; i += stride) {
        int e = i & (NE - 1); int bt = i >> 8;
        g_qemb[i] = emb[(size_t)enc_in[bt] * NE + e];
    }
    for (int i = idx; i < NB*NTD*NE; i += stride) {
        int e = i & (NE - 1); int bt = i >> 8;
        g_remb[i] = emb[(size_t)dec_in[bt] * NE + e];
    }
    for (int i = idx; i < NB*NH; i += stride) {
        g_h[0][i] = 0.f; g_c[0][i] = 0.f; g_attn[i] = 0.f;
    }
    __nv_bfloat16 z = __float2bfloat16(0.f);
    for (int i = idx; i < 512*NH; i += stride) { g_Ahi[i] = z; g_Alo[i] = z; }
    for (int i = idx; i < 128*64; i += stride) { g_flagsE[i] = 0u; g_flagsD[i] = 0u; }
    if (idx == 0) {
        int n = 0;
        for (int b = 0; b < NB; b++) {
            int L = dlen[b]; if (L > NTD) L = NTD; if (L < 0) L = 0;
            for (int t2 = 0; t2 < NTD; t2++) {
                if (t2 < L) { g_outrow[n] = b*NTD + t2; g_rowpos[b*NTD + t2] = n; n++; }
                else g_rowpos[b*NTD + t2] = -1;
            }
        }
        g_nrows = n;
    }
}

// ---------------- permute LSTM weights ----------------
__global__ void permW_kernel(const float* __restrict__ We, const float* __restrict__ Wd)
{
    int idx = blockIdx.x * blockDim.x + threadIdx.x;
    int stride = gridDim.x * blockDim.x;
    for (int i = idx; i < 768*NG; i += stride) {
        int k = i >> 11, g2 = i & (NG - 1);
        int blk = g2 >> 4, x = g2 & 15, jl = x >> 2, q = x & 3;
        g_W2e[i] = We[(size_t)k*NG + q*NH + (blk << 2) + jl];
    }
    for (int i = idx; i < 1280*NG; i += stride) {
        int k = i >> 11, g2 = i & (NG - 1);
        int blk = g2 >> 4, x = g2 & 15, jl = x >> 2, q = x & 3;
        g_W2d[i] = Wd[(size_t)k*NG + q*NH + (blk << 2) + jl];
    }
}

// zero only invalid output rows (valid rows fully written by proj)
__global__ void zero_kernel(float4* __restrict__ out)
{
    int row = blockIdx.y;
    if (g_rowpos[row] >= 0) return;
    int pos = blockIdx.x * 256 + threadIdx.x;
    if (pos < 22500)
        out[(size_t)row * 22500 + pos] = make_float4(0.f, 0.f, 0.f, 0.f);
}

// ---------------- persistent encoder: 512 threads, 32-way k-split ----------------
__global__ void __launch_bounds__(512, 1)
enc_mega(const float* __restrict__ bias, const int* __restrict__ elen)
{
    extern __shared__ float sm[];
    float* xs = sm;                 // [768][PX]
    float* zp = sm + 768*PX;        // [512][PX]
    float* zz = zp + 512*PX;        // [256]

    int tid = threadIdx.x;
    int c = blockIdx.x;
    int gl = tid & 15, s = tid >> 4;       // s 0..31
    int k0 = s * 24;

    float wreg[24];
    {
        const float* Wp = g_W2e + (c << 4) + gl;
        #pragma unroll
        for (int kk = 0; kk < 24; kk++) wreg[kk] = Wp[(size_t)(k0 + kk) * NG];
    }
    float bv = 0.f;
    if (tid < 256) {
        int g2r = tid >> 4;
        bv = bias[(g2r & 3)*NH + (c << 2) + (g2r >> 2)];
    }

    for (int t = 0; t < NTE; t++) {
        const float* h_in  = g_h[t & 1];
        const float* c_in  = g_c[t & 1];
        float* h_out = g_h[(t + 1) & 1];
        float* c_out = g_c[(t + 1) & 1];

        #pragma unroll
        for (int b = 0; b < 16; b++)
            for (int k = tid; k < 768; k += 512) {
                float v = (k < NE) ? g_qemb[(b*NTE + t)*NE + k]
                                   : __ldcg(&h_in[b*NH + (k - NE)]);
                xs[k*PX + b] = v;
            }
        __syncthreads();

        u64 acc[8];
        #pragma unroll
        for (int p = 0; p < 8; p++) acc[p] = 0ULL;
        #pragma unroll
        for (int kk = 0; kk < 24; kk++) {
            u64 w2 = packdup(wreg[kk]);
            const u64* xk = (const u64*)(xs + (k0 + kk)*PX);
            #pragma unroll
            for (int p = 0; p < 8; p++) fma2(acc[p], xk[p], w2);
        }
        #pragma unroll
        for (int p = 0; p < 8; p++) {
            float lo, hi; unpack2(acc[p], lo, hi);
            zp[tid*PX + 2*p]   = lo;
            zp[tid*PX + 2*p+1] = hi;
        }
        __syncthreads();

        if (tid < 256) {
            int g2 = tid >> 4, b = tid & 15;
            float sum = 0.f;
            #pragma unroll
            for (int ss = 0; ss < 32; ss++) sum += zp[(g2 + 16*ss)*PX + b];
            zz[g2*16 + b] = sum + bv;
        }
        __syncthreads();

        if (tid < 64) {
            int jl = tid >> 4, b = tid & 15;
            int jg = (c << 2) + jl;
            float iv = zz[(jl*4 + 0)*16 + b];
            float jv = zz[(jl*4 + 1)*16 + b];
            float fv = zz[(jl*4 + 2)*16 + b];
            float ov = zz[(jl*4 + 3)*16 + b];
            float cold = c_in[b*NH + jg];
            float c2 = cold * fsig(fv + 1.f) + fsig(iv) * ftanh(jv);
            float h2 = ftanh(c2) * fsig(ov);
            bool valid = t < elen[b];
            float hold = xs[(NE + jg)*PX + b];
            h_out[b*NH + jg] = valid ? h2 : hold;
            c_out[b*NH + jg] = valid ? c2 : cold;
            g_encout[((size_t)b*NTE + t)*NH + jg] = valid ? h2 : 0.f;
        }
        gbar3(g_flagsE, c, (unsigned)(t + 1));
    }
}

// ---------------- keys = enc_out @ W_mem ----------------
__global__ void keys_kernel(const float* __restrict__ Wm)
{
    extern __shared__ float sm[];
    const int KX = NH, KP = NH + 4;
    float* xs = sm;
    float* ws = sm + 16*KP;
    int tid = threadIdx.x;
    int cn = blockIdx.x;
    int cr = blockIdx.y;

    for (int i = tid; i < 16*KX; i += 256) {
        int rl = i >> 9, k = i & 511;
        xs[rl*KP + k] = g_encout[(cr*16 + rl)*NH + k];
    }
    for (int i = tid; i < 16*KX; i += 256) {
        int k = i >> 4, nl = i & 15;
        ws[nl*KP + k] = Wm[k*NH + cn*16 + nl];
    }
    __syncthreads();

    int nl = tid & 15, rl = tid >> 4;
    float a0 = 0.f, a1 = 0.f, a2 = 0.f, a3 = 0.f;
    const float* xp = xs + rl*KP;
    const float* wp = ws + nl*KP;
    #pragma unroll 8
    for (int k = 0; k < KX; k += 4) {
        float4 a = *(const float4*)(xp + k);
        float4 w = *(const float4*)(wp + k);
        a0 = fmaf(a.x, w.x, a0);
        a1 = fmaf(a.y, w.y, a1);
        a2 = fmaf(a.z, w.z, a2);
        a3 = fmaf(a.w, w.w, a3);
    }
    g_keys[(cr*16 + rl)*NH + cn*16 + nl] = (a0 + a1) + (a2 + a3);
}

// ---------------- persistent decoder: 512 threads, 5 phases/step ----------------
__global__ void __launch_bounds__(512, 1)
dec_mega(const float* __restrict__ bias, const float* __restrict__ Wq,
         const float* __restrict__ vatt, const float* __restrict__ Wa,
         const int* __restrict__ elen)
{
    extern __shared__ float sm[];
    float* xs  = sm;                    // [1280][PX]
    float* zp  = sm + 1280*PX;          // [512][PX]
    float* zz  = zp + 512*PX;           // [256]
    float* wqs = zz + 256;              // [512][4]
    float* was = wqs + 2048;            // [1024][4]
    float* pqv = sm;                    // P3/P4 aliases (inside xs)
    float* vsv = sm + 512;
    float* scv = sm + 1024;             // 64 scores
    float* ps  = sm + 1088;             // 16 score partials

    int tid = threadIdx.x;
    int c = blockIdx.x;
    int gl = tid & 15, s = tid >> 4;     // s 0..31
    int k0 = s * 40;
    int n0 = c * 4;
    int bq = tid & 15, ks = tid >> 4;    // ks 0..31

    float wreg[40];
    {
        const float* Wp = g_W2d + (c << 4) + gl;
        #pragma unroll
        for (int kk = 0; kk < 40; kk++) wreg[kk] = Wp[(size_t)(k0 + kk) * NG];
    }
    for (int i = tid; i < 512*4; i += 512)
        wqs[i] = Wq[(size_t)(i >> 2)*NH + n0 + (i & 3)];
    for (int i = tid; i < 1024*4; i += 512)
        was[i] = Wa[(size_t)(i >> 2)*NH + n0 + (i & 3)];
    float bv = 0.f;
    if (tid < 256) {
        int g2r = tid >> 4;
        bv = bias[(g2r & 3)*NH + (c << 2) + (g2r >> 2)];
    }
    __syncthreads();

    unsigned idx = 0;
    for (int t = 0; t < NTD; t++) {
        const float* h_in  = g_h[t & 1];
        const float* c_in  = g_c[t & 1];
        float* h_out = g_h[(t + 1) & 1];
        float* c_out = g_c[(t + 1) & 1];

        // ===== P1: LSTM =====
        #pragma unroll
        for (int b = 0; b < 16; b++)
            for (int k = tid; k < 1280; k += 512) {
                float v;
                if (k < NE)           v = g_remb[(b*NTD + t)*NE + k];
                else if (k < NE + NH) v = __ldcg(&g_attn[b*NH + (k - NE)]);
                else                  v = __ldcg(&h_in[b*NH + (k - NE - NH)]);
                xs[k*PX + b] = v;
            }
        __syncthreads();
        {
            u64 acc[8];
            #pragma unroll
            for (int p = 0; p < 8; p++) acc[p] = 0ULL;
            #pragma unroll
            for (int kk = 0; kk < 40; kk++) {
                u64 w2 = packdup(wreg[kk]);
                const u64* xk = (const u64*)(xs + (k0 + kk)*PX);
                #pragma unroll
                for (int p = 0; p < 8; p++) fma2(acc[p], xk[p], w2);
            }
            #pragma unroll
            for (int p = 0; p < 8; p++) {
                float lo, hi; unpack2(acc[p], lo, hi);
                zp[tid*PX + 2*p]   = lo;
                zp[tid*PX + 2*p+1] = hi;
            }
        }
        __syncthreads();
        if (tid < 256) {
            int g2 = tid >> 4, b = tid & 15;
            float sum = 0.f;
            #pragma unroll
            for (int ss = 0; ss < 32; ss++) sum += zp[(g2 + 16*ss)*PX + b];
            zz[g2*16 + b] = sum + bv;
        }
        __syncthreads();
        if (tid < 64) {
            int jl = tid >> 4, b = tid & 15;
            int jg = (c << 2) + jl;
            float iv = zz[(jl*4 + 0)*16 + b];
            float jv = zz[(jl*4 + 1)*16 + b];
            float fv = zz[(jl*4 + 2)*16 + b];
            float ov = zz[(jl*4 + 3)*16 + b];
            float cold = c_in[b*NH + jg];
            float c2 = cold * fsig(fv + 1.f) + fsig(iv) * ftanh(jv);
            float h2 = ftanh(c2) * fsig(ov);
            h_out[b*NH + jg] = h2;
            c_out[b*NH + jg] = c2;
        }
        idx++; gbar3(g_flagsD, c, idx);

        // ===== P2: pq = h2 @ Wq (4 n-cols/CTA, 32-way k-split) =====
        {
            const float4* wq4 = (const float4*)wqs;
            const float* hp = h_out + bq*NH + ks*16;
            float a0 = 0.f, a1 = 0.f, a2 = 0.f, a3 = 0.f;
            #pragma unroll
            for (int kk = 0; kk < 16; kk++) {
                float x = __ldcg(hp + kk);
                float4 w = wq4[ks*16 + kk];
                a0 = fmaf(x, w.x, a0);
                a1 = fmaf(x, w.y, a1);
                a2 = fmaf(x, w.z, a2);
                a3 = fmaf(x, w.w, a3);
            }
            zp[tid*PX + 0] = a0; zp[tid*PX + 1] = a1;
            zp[tid*PX + 2] = a2; zp[tid*PX + 3] = a3;
        }
        __syncthreads();
        if (tid < 64) {
            int bb = tid >> 2, j = tid & 3;
            float sv = 0.f;
            #pragma unroll
            for (int ss = 0; ss < 32; ss++) sv += zp[(bb + 16*ss)*PX + j];
            g_pq[bb*NH + n0 + j] = sv;
        }
        idx++; gbar3(g_flagsD, c, idx);

        // ===== P3: scores (128 CTAs: b = c&15, chunk = c>>4; 2 warps per te) =====
        {
            int b = c & 15, chunk = c >> 4;
            for (int i = tid; i < NH; i += 512) {
                pqv[i] = __ldcg(&g_pq[b*NH + i]);
                vsv[i] = vatt[i];
            }
            __syncthreads();
            int w = tid >> 5, l = tid & 31;
            int half = w & 1;
            int te = chunk*8 + (w >> 1);
            const float* kp = g_keys + ((size_t)b*NTE + te)*NH;
            float p = 0.f;
            #pragma unroll
            for (int j = 0; j < 8; j++) {
                int h = half*32 + l + 64*j;
                p += vsv[h] * ftanh(kp[h] + pqv[h]);
            }
            #pragma unroll
            for (int off = 16; off > 0; off >>= 1) p += __shfl_xor_sync(0xffffffffu, p, off);
            if (l == 0) ps[w] = p;
            __syncthreads();
            if (tid < 8) {
                int te2 = chunk*8 + tid;
                float v = ps[tid*2] + ps[tid*2 + 1];
                int len = elen[b];
                g_score[b*NTE + te2] = (te2 < len) ? v : NEGV;
            }
        }
        idx++; gbar3(g_flagsD, c, idx);

        // ===== P4: softmax + ctx (CTAs 0..15) =====
        if (c < 16) {
            int b = c;
            if (tid < 64) scv[tid] = __ldcg(&g_score[b*NTE + tid]);
            __syncthreads();
            if (tid < 32) {
                float a = scv[tid], b2 = scv[tid + 32];
                float m = fmaxf(a, b2);
                #pragma unroll
                for (int off = 16; off > 0; off >>= 1) m = fmaxf(m, __shfl_xor_sync(0xffffffffu, m, off));
                float e1 = __expf(a - m), e2 = __expf(b2 - m);
                float ssum = e1 + e2;
                #pragma unroll
                for (int off = 16; off > 0; off >>= 1) ssum += __shfl_xor_sync(0xffffffffu, ssum, off);
                float inv = __fdividef(1.f, ssum);
                scv[tid] = e1 * inv; scv[tid + 32] = e2 * inv;
            }
            __syncthreads();
            {
                int h = tid;   // 512 threads cover NH exactly
                float acc = 0.f;
                const float* ep = g_encout + (size_t)b*NTE*NH + h;
                #pragma unroll 8
                for (int te = 0; te < NTE; te++)
                    acc = fmaf(scv[te], ep[(size_t)te*NH], acc);
                g_ctx[b*NH + h] = acc;
            }
        }
        idx++; gbar3(g_flagsD, c, idx);

        // ===== P5: attn2 = [h2|ctx] @ Wa, write attn + bf16 A =====
        {
            const float4* wa4 = (const float4*)was;
            const float* src = (ks < 16) ? (h_out + bq*NH + ks*32)
                                         : (g_ctx + bq*NH + (ks - 16)*32);
            float a0 = 0.f, a1 = 0.f, a2 = 0.f, a3 = 0.f;
            #pragma unroll
            for (int kk = 0; kk < 32; kk++) {
                float x = __ldcg(src + kk);
                float4 w = wa4[ks*32 + kk];
                a0 = fmaf(x, w.x, a0);
                a1 = fmaf(x, w.y, a1);
                a2 = fmaf(x, w.z, a2);
                a3 = fmaf(x, w.w, a3);
            }
            zp[tid*PX + 0] = a0; zp[tid*PX + 1] = a1;
            zp[tid*PX + 2] = a2; zp[tid*PX + 3] = a3;
        }
        __syncthreads();
        if (tid < 64) {
            int bb = tid >> 2, j = tid & 3;
            float sv = 0.f;
            #pragma unroll
            for (int ss = 0; ss < 32; ss++) sv += zp[(bb + 16*ss)*PX + j];
            g_attn[bb*NH + n0 + j] = sv;
            int m = g_rowpos[bb*NTD + t];
            if (m >= 0) {
                __nv_bfloat16 hi = __float2bfloat16(sv);
                g_Ahi[m*NH + n0 + j] = hi;
                g_Alo[m*NH + n0 + j] = __float2bfloat16(sv - __bfloat162float(hi));
            }
        }
        idx++; gbar3(g_flagsD, c, idx);
    }
}

// ---------------- HMMA projection with in-kernel W conversion ----------------
#define PR_LDA 72
#define PROJ_SMEM (4*128*PR_LDA*2)

__device__ __forceinline__ void ldmA(uint32_t* a, uint32_t addr) {
    asm volatile("ldmatrix.sync.aligned.m8n8.x4.shared.b16 {%0,%1,%2,%3}, [%4];"
                 : "=r"(a[0]), "=r"(a[1]), "=r"(a[2]), "=r"(a[3]) : "r"(addr));
}
__device__ __forceinline__ void ldmB(uint32_t* b, uint32_t addr) {
    asm volatile("ldmatrix.sync.aligned.m8n8.x2.shared.b16 {%0,%1}, [%2];"
                 : "=r"(b[0]), "=r"(b[1]) : "r"(addr));
}
__device__ __forceinline__ void mma16816(float* c, const uint32_t* a, const uint32_t* b) {
    asm volatile("mma.sync.aligned.m16n8k16.row.col.f32.bf16.bf16.f32 "
                 "{%0,%1,%2,%3}, {%4,%5,%6,%7}, {%8,%9}, {%0,%1,%2,%3};"
                 : "+f"(c[0]), "+f"(c[1]), "+f"(c[2]), "+f"(c[3])
                 : "r"(a[0]), "r"(a[1]), "r"(a[2]), "r"(a[3]), "r"(b[0]), "r"(b[1]));
}

__global__ void __launch_bounds__(256, 1)
proj_hmma(const float* __restrict__ Wp, float* __restrict__ out)
{
    extern __shared__ __nv_bfloat16 smb[];
    __nv_bfloat16* sAhi = smb;
    __nv_bfloat16* sAlo = smb + 128*PR_LDA;
    __nv_bfloat16* sBhi = smb + 2*128*PR_LDA;
    __nv_bfloat16* sBlo = smb + 3*128*PR_LDA;

    int m0 = blockIdx.x * 128;
    int n0 = blockIdx.y * 128;
    int nr = g_nrows;
    if (m0 >= nr) return;

    int tid = threadIdx.x;
    int wid = tid >> 5, lane = tid & 31;
    int m0w = (wid >> 2) * 64;
    int n0w = (wid & 3) * 32;

    uint32_t sb = smem_u32(smb);
    uint32_t aAhi = sb, aAlo = sb + 128*PR_LDA*2, aBhi = sb + 2*128*PR_LDA*2, aBlo = sb + 3*128*PR_LDA*2;

    float c[4][4][4];
    #pragma unroll
    for (int i = 0; i < 4; i++)
        #pragma unroll
        for (int j = 0; j < 4; j++)
            #pragma unroll
            for (int q = 0; q < 4; q++) c[i][j][q] = 0.f;

    for (int ch = 0; ch < 8; ch++) {
        int k0 = ch * 64;
        // A: already bf16 hi/lo in gmem
        for (int i = tid; i < 1024; i += 256) {
            int m = i >> 3, kb = i & 7;
            size_t go = (size_t)(m0 + m)*NH + k0 + kb*8;
            int so = m*PR_LDA + kb*8;
            *(uint4*)&sAhi[so] = *(const uint4*)&g_Ahi[go];
            *(uint4*)&sAlo[so] = *(const uint4*)&g_Alo[go];
        }
        // B: read fp32 W_proj [k][v], convert to bf16 hi/lo, store [n][k]
        for (int i = tid; i < 4096; i += 256) {
            int n = i & 127, kkp = i >> 7;     // kkp 0..31
            int kk = kkp * 2;
            int nn = n0 + n;
            float w0 = 0.f, w1 = 0.f;
            if (nn < NV) {
                w0 = Wp[(size_t)(k0 + kk)*NV + nn];
                w1 = Wp[(size_t)(k0 + kk + 1)*NV + nn];
            }
            __nv_bfloat16 h0 = __float2bfloat16(w0);
            __nv_bfloat16 h1 = __float2bfloat16(w1);
            float r0 = w0 - __bfloat162float(h0);
            float r1 = w1 - __bfloat162float(h1);
            __nv_bfloat16 l0 = __float2bfloat16(r0);
            __nv_bfloat16 l1 = __float2bfloat16(r1);
            uint32_t hv = (uint32_t)__bfloat16_as_ushort(h0) |
                          ((uint32_t)__bfloat16_as_ushort(h1) << 16);
            uint32_t lv = (uint32_t)__bfloat16_as_ushort(l0) |
                          ((uint32_t)__bfloat16_as_ushort(l1) << 16);
            int so = n*PR_LDA + kk;
            *(uint32_t*)&sBhi[so] = hv;
            *(uint32_t*)&sBlo[so] = lv;
        }
        __syncthreads();

        #pragma unroll
        for (int ksp = 0; ksp < 4; ksp++) {
            int kp = ksp * 16;
            uint32_t ahi[4][4], alo[4][4], bhi[4][2], blo[4][2];
            #pragma unroll
            for (int mt = 0; mt < 4; mt++) {
                uint32_t off = ((m0w + mt*16 + (lane & 15)) * PR_LDA + kp + ((lane >> 4) << 3)) * 2;
                ldmA(ahi[mt], aAhi + off);
                ldmA(alo[mt], aAlo + off);
            }
            #pragma unroll
            for (int nt = 0; nt < 4; nt++) {
                uint32_t off = ((n0w + nt*8 + (lane & 7)) * PR_LDA + kp + (((lane >> 3) & 1) << 3)) * 2;
                ldmB(bhi[nt], aBhi + off);
                ldmB(blo[nt], aBlo + off);
            }
            #pragma unroll
            for (int mt = 0; mt < 4; mt++)
                #pragma unroll
                for (int nt = 0; nt < 4; nt++) {
                    mma16816(c[mt][nt], ahi[mt], bhi[nt]);
                    mma16816(c[mt][nt], ahi[mt], blo[nt]);
                    mma16816(c[mt][nt], alo[mt], bhi[nt]);
                }
        }
        __syncthreads();
    }

    int rg = lane >> 2, cg = (lane & 3) * 2;
    #pragma unroll
    for (int mt = 0; mt < 4; mt++) {
        #pragma unroll
        for (int half = 0; half < 2; half++) {
            int mloc = m0w + mt*16 + rg + half*8;
            int m = m0 + mloc;
            if (m < nr) {
                int orow = g_outrow[m];
                float* obase = out + (size_t)orow*NV;
                #pragma unroll
                for (int nt = 0; nt < 4; nt++) {
                    int nn = n0 + n0w + nt*8 + cg;
                    float v0 = c[mt][nt][half*2 + 0];
                    float v1 = c[mt][nt][half*2 + 1];
                    if (nn + 1 < NV) {
                        *(float2*)(obase + nn) = make_float2(v0, v1);
                    } else if (nn < NV) {
                        obase[nn] = v0;
                    }
                }
            }
        }
    }
}

// ---------------- launch ----------------
extern "C" void kernel_launch(void* const* d_in, const int* in_sizes, int n_in,
                              void* d_out, int out_size)
{
    const int*   enc_in  = (const int*)d_in[0];
    const int*   dec_in  = (const int*)d_in[1];
    const int*   elen    = (const int*)d_in[2];
    const int*   dlen    = (const int*)d_in[3];
    const float* emb     = (const float*)d_in[4];
    const float* W_enc   = (const float*)d_in[5];
    const float* b_enc   = (const float*)d_in[6];
    const float* W_dec   = (const float*)d_in[7];
    const float* b_dec   = (const float*)d_in[8];
    const float* W_mem   = (const float*)d_in[9];
    const float* W_query = (const float*)d_in[10];
    const float* v_att   = (const float*)d_in[11];
    const float* W_attn  = (const float*)d_in[12];
    const float* W_proj  = (const float*)d_in[13];
    float* out = (float*)d_out;

    const int smemE = (768*PX + 512*PX + 256) * 4;                   //  93,184 B
    const int smemD = (1280*PX + 512*PX + 256 + 2048 + 4096) * 4;    // 154,624 B
    const int smemK = (2*16*(NH + 4)) * 4;                           //  66,048 B

    cudaFuncSetAttribute(enc_mega,    cudaFuncAttributeMaxDynamicSharedMemorySize, smemE);
    cudaFuncSetAttribute(dec_mega,    cudaFuncAttributeMaxDynamicSharedMemorySize, smemD);
    cudaFuncSetAttribute(keys_kernel, cudaFuncAttributeMaxDynamicSharedMemorySize, smemK);
    cudaFuncSetAttribute(proj_hmma,   cudaFuncAttributeMaxDynamicSharedMemorySize, PROJ_SMEM);

    prep_kernel<<<256, 256>>>(enc_in, dec_in, dlen, emb);
    permW_kernel<<<512, 256>>>(W_enc, W_dec);
    zero_kernel<<<dim3(88, 512), 256>>>((float4*)out);

    enc_mega<<<128, 512, smemE>>>(b_enc, elen);
    keys_kernel<<<dim3(32, 64), 256, smemK>>>(W_mem);
    dec_mega<<<128, 512, smemD>>>(b_dec, W_query, v_att, W_attn, elen);

    proj_hmma<<<dim3(4, 704), 256, PROJ_SMEM>>>(W_proj, out);
}

// round 11
// speedup vs baseline: 1.4786x; 1.0525x over previous
#include <cuda_runtime.h>
#include <cuda_bf16.h>
#include <math.h>
#include <stdint.h>

#define NB 16
#define NTE 64
#define NTD 32
#define NE 256
#define NH 512
#define NG 2048
#define NV 90000
#define NEGV (-1e9f)
#define PX 18

typedef unsigned long long u64;

// ---------------- device scratch ----------------
__device__ float g_qemb[NB*NTE*NE];
__device__ float g_remb[NB*NTD*NE];
__device__ float g_h[2][NB*NH];
__device__ float g_c[2][NB*NH];
__device__ float g_attn[NB*NH];
__device__ float g_encout[NB*NTE*NH];
__device__ float g_keys[NB*NTE*NH];
__device__ float g_pq[NB*NH];
__device__ float g_ctx[NB*NH];
__device__ int   g_outrow[NB*NTD];
__device__ int   g_rowpos[NB*NTD];
__device__ int   g_nrows;
__device__ float g_W2e[768*NG];
__device__ float g_W2d[1280*NG];
__device__ __nv_bfloat16 g_Ahi[512*NH];
__device__ __nv_bfloat16 g_Alo[512*NH];

// ---------------- fast math ----------------
__device__ __forceinline__ float fsig(float x) {
    return __fdividef(1.f, 1.f + __expf(-x));
}
__device__ __forceinline__ float ftanh(float x) {
    x = fminf(fmaxf(x, -15.f), 15.f);
    float a = __expf(2.f * x);
    return __fdividef(a - 1.f, a + 1.f);
}

__device__ __forceinline__ u64 packdup(float v) {
    u64 r;
    asm("mov.b64 %0, {%1, %1};" : "=l"(r) : "r"(__float_as_uint(v)));
    return r;
}
__device__ __forceinline__ void fma2(u64& d, u64 a, u64 b) {
    asm("fma.rn.f32x2 %0, %1, %2, %0;" : "+l"(d) : "l"(a), "l"(b));
}
__device__ __forceinline__ void unpack2(u64 v, float& lo, float& hi) {
    unsigned l, h;
    asm("mov.b64 {%0, %1}, %2;" : "=r"(l), "=r"(h) : "l"(v));
    lo = __uint_as_float(l); hi = __uint_as_float(h);
}
__device__ __forceinline__ uint32_t smem_u32(const void* p) {
    uint32_t a;
    asm("{ .reg .u64 t; cvta.to.shared.u64 t, %1; cvt.u32.u64 %0, t; }" : "=r"(a) : "l"(p));
    return a;
}

// ---------------- prep ----------------
__global__ void prep_kernel(const int* __restrict__ enc_in, const int* __restrict__ dec_in,
                            const int* __restrict__ dlen, const float* __restrict__ emb)
{
    int idx = blockIdx.x * blockDim.x + threadIdx.x;
    int stride = gridDim.x * blockDim.x;
    for (int i = idx; i < NB*NTE*NE; i += stride) {
        int e = i & (NE - 1); int bt = i >> 8;
        g_qemb[i] = emb[(size_t)enc_in[bt] * NE + e];
    }
    for (int i = idx; i < NB*NTD*NE; i += stride) {
        int e = i & (NE - 1); int bt = i >> 8;
        g_remb[i] = emb[(size_t)dec_in[bt] * NE + e];
    }
    for (int i = idx; i < NB*NH; i += stride) {
        g_h[0][i] = 0.f; g_c[0][i] = 0.f; g_attn[i] = 0.f;
    }
    __nv_bfloat16 z = __float2bfloat16(0.f);
    for (int i = idx; i < 512*NH; i += stride) { g_Ahi[i] = z; g_Alo[i] = z; }
    if (idx == 0) {
        int n = 0;
        for (int b = 0; b < NB; b++) {
            int L = dlen[b]; if (L > NTD) L = NTD; if (L < 0) L = 0;
            for (int t2 = 0; t2 < NTD; t2++) {
                if (t2 < L) { g_outrow[n] = b*NTD + t2; g_rowpos[b*NTD + t2] = n; n++; }
                else g_rowpos[b*NTD + t2] = -1;
            }
        }
        g_nrows = n;
    }
}

// ---------------- permute LSTM weights: W2[k][blk*16 + jl*4 + q] ----------------
__global__ void permW_kernel(const float* __restrict__ We, const float* __restrict__ Wd)
{
    int idx = blockIdx.x * blockDim.x + threadIdx.x;
    int stride = gridDim.x * blockDim.x;
    for (int i = idx; i < 768*NG; i += stride) {
        int k = i >> 11, g2 = i & (NG - 1);
        int blk = g2 >> 4, x = g2 & 15, jl = x >> 2, q = x & 3;
        g_W2e[i] = We[(size_t)k*NG + q*NH + (blk << 2) + jl];
    }
    for (int i = idx; i < 1280*NG; i += stride) {
        int k = i >> 11, g2 = i & (NG - 1);
        int blk = g2 >> 4, x = g2 & 15, jl = x >> 2, q = x & 3;
        g_W2d[i] = Wd[(size_t)k*NG + q*NH + (blk << 2) + jl];
    }
}

// zero only invalid output rows
__global__ void zero_kernel(float4* __restrict__ out)
{
    int row = blockIdx.y;
    if (g_rowpos[row] >= 0) return;
    int pos = blockIdx.x * 256 + threadIdx.x;
    if (pos < 22500)
        out[(size_t)row * 22500 + pos] = make_float4(0.f, 0.f, 0.f, 0.f);
}

// ---------------- encoder step: 128 CTAs x 512 thr, launched per t ----------------
__global__ void __launch_bounds__(512, 1)
enc_step(const float* __restrict__ bias, const int* __restrict__ elen, int t)
{
    extern __shared__ float sm[];
    float* xs = sm;                 // [768][PX]
    float* zp = sm + 768*PX;        // [512][PX]
    float* zz = zp + 512*PX;        // [256]

    int tid = threadIdx.x;
    int c = blockIdx.x;
    int gl = tid & 15, s = tid >> 4;
    int k0 = s * 24;

    const float* h_in  = g_h[t & 1];
    const float* c_in  = g_c[t & 1];
    float* h_out = g_h[(t + 1) & 1];
    float* c_out = g_c[(t + 1) & 1];

    // stage x = [emb | h], transposed [k][b]
    #pragma unroll
    for (int b = 0; b < 16; b++)
        for (int k = tid; k < 768; k += 512) {
            float v = (k < NE) ? g_qemb[(b*NTE + t)*NE + k] : h_in[b*NH + (k - NE)];
            xs[k*PX + b] = v;
        }

    float wreg[24];
    {
        const float* Wp = g_W2e + (c << 4) + gl;
        #pragma unroll
        for (int kk = 0; kk < 24; kk++) wreg[kk] = __ldg(Wp + (size_t)(k0 + kk) * NG);
    }
    __syncthreads();

    u64 acc[8];
    #pragma unroll
    for (int p = 0; p < 8; p++) acc[p] = 0ULL;
    #pragma unroll
    for (int kk = 0; kk < 24; kk++) {
        u64 w2 = packdup(wreg[kk]);
        const u64* xk = (const u64*)(xs + (k0 + kk)*PX);
        #pragma unroll
        for (int p = 0; p < 8; p++) fma2(acc[p], xk[p], w2);
    }
    #pragma unroll
    for (int p = 0; p < 8; p++) {
        float lo, hi; unpack2(acc[p], lo, hi);
        zp[tid*PX + 2*p]   = lo;
        zp[tid*PX + 2*p+1] = hi;
    }
    __syncthreads();

    if (tid < 256) {
        int g2 = tid >> 4, b = tid & 15;
        float sum = 0.f;
        #pragma unroll
        for (int ss = 0; ss < 32; ss++) sum += zp[(g2 + 16*ss)*PX + b];
        zz[g2*16 + b] = sum + bias[(g2 & 3)*NH + (c << 2) + (g2 >> 2)];
    }
    __syncthreads();

    if (tid < 64) {
        int jl = tid >> 4, b = tid & 15;
        int jg = (c << 2) + jl;
        float iv = zz[(jl*4 + 0)*16 + b];
        float jv = zz[(jl*4 + 1)*16 + b];
        float fv = zz[(jl*4 + 2)*16 + b];
        float ov = zz[(jl*4 + 3)*16 + b];
        float cold = c_in[b*NH + jg];
        float c2 = cold * fsig(fv + 1.f) + fsig(iv) * ftanh(jv);
        float h2 = ftanh(c2) * fsig(ov);
        bool valid = t < elen[b];
        float hold = xs[(NE + jg)*PX + b];
        h_out[b*NH + jg] = valid ? h2 : hold;
        c_out[b*NH + jg] = valid ? c2 : cold;
        g_encout[((size_t)b*NTE + t)*NH + jg] = valid ? h2 : 0.f;
    }
}

// ---------------- keys = enc_out @ W_mem ----------------
__global__ void keys_kernel(const float* __restrict__ Wm)
{
    extern __shared__ float sm[];
    const int KX = NH, KP = NH + 4;
    float* xs = sm;
    float* ws = sm + 16*KP;
    int tid = threadIdx.x;
    int cn = blockIdx.x;
    int cr = blockIdx.y;

    for (int i = tid; i < 16*KX; i += 256) {
        int rl = i >> 9, k = i & 511;
        xs[rl*KP + k] = g_encout[(cr*16 + rl)*NH + k];
    }
    for (int i = tid; i < 16*KX; i += 256) {
        int k = i >> 4, nl = i & 15;
        ws[nl*KP + k] = Wm[k*NH + cn*16 + nl];
    }
    __syncthreads();

    int nl = tid & 15, rl = tid >> 4;
    float a0 = 0.f, a1 = 0.f, a2 = 0.f, a3 = 0.f;
    const float* xp = xs + rl*KP;
    const float* wp = ws + nl*KP;
    #pragma unroll 8
    for (int k = 0; k < KX; k += 4) {
        float4 a = *(const float4*)(xp + k);
        float4 w = *(const float4*)(wp + k);
        a0 = fmaf(a.x, w.x, a0);
        a1 = fmaf(a.y, w.y, a1);
        a2 = fmaf(a.z, w.z, a2);
        a3 = fmaf(a.w, w.w, a3);
    }
    g_keys[(cr*16 + rl)*NH + cn*16 + nl] = (a0 + a1) + (a2 + a3);
}

// ---------------- decoder LSTM step: 128 CTAs x 512 thr ----------------
__global__ void __launch_bounds__(512, 1)
dec_lstm(const float* __restrict__ bias, int t)
{
    extern __shared__ float sm[];
    float* xs = sm;                 // [1280][PX]
    float* zp = sm + 1280*PX;       // [512][PX]
    float* zz = zp + 512*PX;        // [256]

    int tid = threadIdx.x;
    int c = blockIdx.x;
    int gl = tid & 15, s = tid >> 4;
    int k0 = s * 40;

    const float* h_in  = g_h[t & 1];
    const float* c_in  = g_c[t & 1];
    float* h_out = g_h[(t + 1) & 1];
    float* c_out = g_c[(t + 1) & 1];

    #pragma unroll
    for (int b = 0; b < 16; b++)
        for (int k = tid; k < 1280; k += 512) {
            float v;
            if (k < NE)           v = g_remb[(b*NTD + t)*NE + k];
            else if (k < NE + NH) v = g_attn[b*NH + (k - NE)];
            else                  v = h_in[b*NH + (k - NE - NH)];
            xs[k*PX + b] = v;
        }

    float wreg[40];
    {
        const float* Wp = g_W2d + (c << 4) + gl;
        #pragma unroll
        for (int kk = 0; kk < 40; kk++) wreg[kk] = __ldg(Wp + (size_t)(k0 + kk) * NG);
    }
    __syncthreads();

    u64 acc[8];
    #pragma unroll
    for (int p = 0; p < 8; p++) acc[p] = 0ULL;
    #pragma unroll
    for (int kk = 0; kk < 40; kk++) {
        u64 w2 = packdup(wreg[kk]);
        const u64* xk = (const u64*)(xs + (k0 + kk)*PX);
        #pragma unroll
        for (int p = 0; p < 8; p++) fma2(acc[p], xk[p], w2);
    }
    #pragma unroll
    for (int p = 0; p < 8; p++) {
        float lo, hi; unpack2(acc[p], lo, hi);
        zp[tid*PX + 2*p]   = lo;
        zp[tid*PX + 2*p+1] = hi;
    }
    __syncthreads();

    if (tid < 256) {
        int g2 = tid >> 4, b = tid & 15;
        float sum = 0.f;
        #pragma unroll
        for (int ss = 0; ss < 32; ss++) sum += zp[(g2 + 16*ss)*PX + b];
        zz[g2*16 + b] = sum + bias[(g2 & 3)*NH + (c << 2) + (g2 >> 2)];
    }
    __syncthreads();

    if (tid < 64) {
        int jl = tid >> 4, b = tid & 15;
        int jg = (c << 2) + jl;
        float iv = zz[(jl*4 + 0)*16 + b];
        float jv = zz[(jl*4 + 1)*16 + b];
        float fv = zz[(jl*4 + 2)*16 + b];
        float ov = zz[(jl*4 + 3)*16 + b];
        float cold = c_in[b*NH + jg];
        float c2 = cold * fsig(fv + 1.f) + fsig(iv) * ftanh(jv);
        float h2 = ftanh(c2) * fsig(ov);
        h_out[b*NH + jg] = h2;
        c_out[b*NH + jg] = c2;
    }
}

// ---------------- pq = h2 @ Wq : 128 CTAs x 256 thr (4 n-cols per CTA) ----------------
__global__ void __launch_bounds__(256, 2)
dec_pq(const float* __restrict__ Wq, int t)
{
    __shared__ float zp[256*4];
    int tid = threadIdx.x;
    int c = blockIdx.x;
    int n0 = c * 4;
    int bq = tid & 15, ks = tid >> 4;    // ks 0..15, 32 k each
    const float* h2 = g_h[(t + 1) & 1];

    const float* hp = h2 + bq*NH + ks*32;
    const float4* wq4 = (const float4*)(Wq + n0);
    float a0 = 0.f, a1 = 0.f, a2 = 0.f, a3 = 0.f;
    #pragma unroll
    for (int kk = 0; kk < 32; kk++) {
        float x = hp[kk];
        float4 w = __ldg(wq4 + (size_t)(ks*32 + kk)*(NH/4));
        a0 = fmaf(x, w.x, a0);
        a1 = fmaf(x, w.y, a1);
        a2 = fmaf(x, w.z, a2);
        a3 = fmaf(x, w.w, a3);
    }
    zp[tid*4 + 0] = a0; zp[tid*4 + 1] = a1;
    zp[tid*4 + 2] = a2; zp[tid*4 + 3] = a3;
    __syncthreads();

    if (tid < 64) {
        int bb = tid >> 2, j = tid & 3;
        float sv = 0.f;
        #pragma unroll
        for (int ss = 0; ss < 16; ss++) sv += zp[(bb + 16*ss)*4 + j];
        g_pq[bb*NH + n0 + j] = sv;
    }
}

// ---------------- scores + softmax + ctx : 16 CTAs x 512 thr ----------------
__global__ void __launch_bounds__(512, 1)
dec_att(const float* __restrict__ vatt, const int* __restrict__ elen, int t)
{
    __shared__ float pqv[NH];
    __shared__ float vsv[NH];
    __shared__ float scv[NTE];

    int tid = threadIdx.x;
    int b = blockIdx.x;

    pqv[tid] = g_pq[b*NH + tid];
    vsv[tid] = vatt[tid];
    __syncthreads();

    // scores: 16 warps, 4 te each
    int w = tid >> 5, l = tid & 31;
    int len = elen[b];
    #pragma unroll
    for (int r = 0; r < 4; r++) {
        int te = w*4 + r;
        const float* kp = g_keys + ((size_t)b*NTE + te)*NH;
        float p = 0.f;
        #pragma unroll
        for (int j = 0; j < 16; j++) {
            int h = l + 32*j;
            p += vsv[h] * ftanh(kp[h] + pqv[h]);
        }
        #pragma unroll
        for (int off = 16; off > 0; off >>= 1) p += __shfl_xor_sync(0xffffffffu, p, off);
        if (l == 0) scv[te] = (te < len) ? p : NEGV;
    }
    __syncthreads();

    if (tid < 32) {
        float a = scv[tid], b2 = scv[tid + 32];
        float m = fmaxf(a, b2);
        #pragma unroll
        for (int off = 16; off > 0; off >>= 1) m = fmaxf(m, __shfl_xor_sync(0xffffffffu, m, off));
        float e1 = __expf(a - m), e2 = __expf(b2 - m);
        float ssum = e1 + e2;
        #pragma unroll
        for (int off = 16; off > 0; off >>= 1) ssum += __shfl_xor_sync(0xffffffffu, ssum, off);
        float inv = __fdividef(1.f, ssum);
        scv[tid] = e1 * inv; scv[tid + 32] = e2 * inv;
    }
    __syncthreads();

    {
        int h = tid;
        float acc = 0.f;
        const float* ep = g_encout + (size_t)b*NTE*NH + h;
        #pragma unroll 8
        for (int te = 0; te < NTE; te++)
            acc = fmaf(scv[te], ep[(size_t)te*NH], acc);
        g_ctx[b*NH + h] = acc;
    }
}

// ---------------- attn2 = [h2|ctx] @ Wa : 128 CTAs x 256 thr, writes attn + bf16 A ----------------
__global__ void __launch_bounds__(256, 2)
dec_attn2(const float* __restrict__ Wa, int t)
{
    __shared__ float zp[256*4];
    int tid = threadIdx.x;
    int c = blockIdx.x;
    int n0 = c * 4;
    int bq = tid & 15, ks = tid >> 4;    // ks 0..15, 64 k each over K=1024
    const float* h2 = g_h[(t + 1) & 1];

    const float* src = (ks < 8) ? (h2 + bq*NH + ks*64)
                                : (g_ctx + bq*NH + (ks - 8)*64);
    const float4* wa4 = (const float4*)(Wa + n0);
    float a0 = 0.f, a1 = 0.f, a2 = 0.f, a3 = 0.f;
    #pragma unroll
    for (int kk = 0; kk < 64; kk++) {
        float x = src[kk];
        float4 w = __ldg(wa4 + (size_t)(ks*64 + kk)*(NH/4));
        a0 = fmaf(x, w.x, a0);
        a1 = fmaf(x, w.y, a1);
        a2 = fmaf(x, w.z, a2);
        a3 = fmaf(x, w.w, a3);
    }
    zp[tid*4 + 0] = a0; zp[tid*4 + 1] = a1;
    zp[tid*4 + 2] = a2; zp[tid*4 + 3] = a3;
    __syncthreads();

    if (tid < 64) {
        int bb = tid >> 2, j = tid & 3;
        float sv = 0.f;
        #pragma unroll
        for (int ss = 0; ss < 16; ss++) sv += zp[(bb + 16*ss)*4 + j];
        g_attn[bb*NH + n0 + j] = sv;
        int m = g_rowpos[bb*NTD + t];
        if (m >= 0) {
            __nv_bfloat16 hi = __float2bfloat16(sv);
            g_Ahi[m*NH + n0 + j] = hi;
            g_Alo[m*NH + n0 + j] = __float2bfloat16(sv - __bfloat162float(hi));
        }
    }
}

// ---------------- HMMA projection with in-kernel W conversion ----------------
#define PR_LDA 72
#define PROJ_SMEM (4*128*PR_LDA*2)

__device__ __forceinline__ void ldmA(uint32_t* a, uint32_t addr) {
    asm volatile("ldmatrix.sync.aligned.m8n8.x4.shared.b16 {%0,%1,%2,%3}, [%4];"
                 : "=r"(a[0]), "=r"(a[1]), "=r"(a[2]), "=r"(a[3]) : "r"(addr));
}
__device__ __forceinline__ void ldmB(uint32_t* b, uint32_t addr) {
    asm volatile("ldmatrix.sync.aligned.m8n8.x2.shared.b16 {%0,%1}, [%2];"
                 : "=r"(b[0]), "=r"(b[1]) : "r"(addr));
}
__device__ __forceinline__ void mma16816(float* c, const uint32_t* a, const uint32_t* b) {
    asm volatile("mma.sync.aligned.m16n8k16.row.col.f32.bf16.bf16.f32 "
                 "{%0,%1,%2,%3}, {%4,%5,%6,%7}, {%8,%9}, {%0,%1,%2,%3};"
                 : "+f"(c[0]), "+f"(c[1]), "+f"(c[2]), "+f"(c[3])
                 : "r"(a[0]), "r"(a[1]), "r"(a[2]), "r"(a[3]), "r"(b[0]), "r"(b[1]));
}

__global__ void __launch_bounds__(256, 1)
proj_hmma(const float* __restrict__ Wp, float* __restrict__ out)
{
    extern __shared__ __nv_bfloat16 smb[];
    __nv_bfloat16* sAhi = smb;
    __nv_bfloat16* sAlo = smb + 128*PR_LDA;
    __nv_bfloat16* sBhi = smb + 2*128*PR_LDA;
    __nv_bfloat16* sBlo = smb + 3*128*PR_LDA;

    int m0 = blockIdx.x * 128;
    int n0 = blockIdx.y * 128;
    int nr = g_nrows;
    if (m0 >= nr) return;

    int tid = threadIdx.x;
    int wid = tid >> 5, lane = tid & 31;
    int m0w = (wid >> 2) * 64;
    int n0w = (wid & 3) * 32;

    uint32_t sb = smem_u32(smb);
    uint32_t aAhi = sb, aAlo = sb + 128*PR_LDA*2, aBhi = sb + 2*128*PR_LDA*2, aBlo = sb + 3*128*PR_LDA*2;

    float c[4][4][4];
    #pragma unroll
    for (int i = 0; i < 4; i++)
        #pragma unroll
        for (int j = 0; j < 4; j++)
            #pragma unroll
            for (int q = 0; q < 4; q++) c[i][j][q] = 0.f;

    for (int ch = 0; ch < 8; ch++) {
        int k0 = ch * 64;
        for (int i = tid; i < 1024; i += 256) {
            int m = i >> 3, kb = i & 7;
            size_t go = (size_t)(m0 + m)*NH + k0 + kb*8;
            int so = m*PR_LDA + kb*8;
            *(uint4*)&sAhi[so] = *(const uint4*)&g_Ahi[go];
            *(uint4*)&sAlo[so] = *(const uint4*)&g_Alo[go];
        }
        for (int i = tid; i < 4096; i += 256) {
            int n = i & 127, kkp = i >> 7;
            int kk = kkp * 2;
            int nn = n0 + n;
            float w0 = 0.f, w1 = 0.f;
            if (nn < NV) {
                w0 = Wp[(size_t)(k0 + kk)*NV + nn];
                w1 = Wp[(size_t)(k0 + kk + 1)*NV + nn];
            }
            __nv_bfloat16 h0 = __float2bfloat16(w0);
            __nv_bfloat16 h1 = __float2bfloat16(w1);
            float r0 = w0 - __bfloat162float(h0);
            float r1 = w1 - __bfloat162float(h1);
            __nv_bfloat16 l0 = __float2bfloat16(r0);
            __nv_bfloat16 l1 = __float2bfloat16(r1);
            uint32_t hv = (uint32_t)__bfloat16_as_ushort(h0) |
                          ((uint32_t)__bfloat16_as_ushort(h1) << 16);
            uint32_t lv = (uint32_t)__bfloat16_as_ushort(l0) |
                          ((uint32_t)__bfloat16_as_ushort(l1) << 16);
            int so = n*PR_LDA + kk;
            *(uint32_t*)&sBhi[so] = hv;
            *(uint32_t*)&sBlo[so] = lv;
        }
        __syncthreads();

        #pragma unroll
        for (int ksp = 0; ksp < 4; ksp++) {
            int kp = ksp * 16;
            uint32_t ahi[4][4], alo[4][4], bhi[4][2], blo[4][2];
            #pragma unroll
            for (int mt = 0; mt < 4; mt++) {
                uint32_t off = ((m0w + mt*16 + (lane & 15)) * PR_LDA + kp + ((lane >> 4) << 3)) * 2;
                ldmA(ahi[mt], aAhi + off);
                ldmA(alo[mt], aAlo + off);
            }
            #pragma unroll
            for (int nt = 0; nt < 4; nt++) {
                uint32_t off = ((n0w + nt*8 + (lane & 7)) * PR_LDA + kp + (((lane >> 3) & 1) << 3)) * 2;
                ldmB(bhi[nt], aBhi + off);
                ldmB(blo[nt], aBlo + off);
            }
            #pragma unroll
            for (int mt = 0; mt < 4; mt++)
                #pragma unroll
                for (int nt = 0; nt < 4; nt++) {
                    mma16816(c[mt][nt], ahi[mt], bhi[nt]);
                    mma16816(c[mt][nt], ahi[mt], blo[nt]);
                    mma16816(c[mt][nt], alo[mt], bhi[nt]);
                }
        }
        __syncthreads();
    }

    int rg = lane >> 2, cg = (lane & 3) * 2;
    #pragma unroll
    for (int mt = 0; mt < 4; mt++) {
        #pragma unroll
        for (int half = 0; half < 2; half++) {
            int mloc = m0w + mt*16 + rg + half*8;
            int m = m0 + mloc;
            if (m < nr) {
                int orow = g_outrow[m];
                float* obase = out + (size_t)orow*NV;
                #pragma unroll
                for (int nt = 0; nt < 4; nt++) {
                    int nn = n0 + n0w + nt*8 + cg;
                    float v0 = c[mt][nt][half*2 + 0];
                    float v1 = c[mt][nt][half*2 + 1];
                    if (nn + 1 < NV) {
                        *(float2*)(obase + nn) = make_float2(v0, v1);
                    } else if (nn < NV) {
                        obase[nn] = v0;
                    }
                }
            }
        }
    }
}

// ---------------- launch ----------------
extern "C" void kernel_launch(void* const* d_in, const int* in_sizes, int n_in,
                              void* d_out, int out_size)
{
    const int*   enc_in  = (const int*)d_in[0];
    const int*   dec_in  = (const int*)d_in[1];
    const int*   elen    = (const int*)d_in[2];
    const int*   dlen    = (const int*)d_in[3];
    const float* emb     = (const float*)d_in[4];
    const float* W_enc   = (const float*)d_in[5];
    const float* b_enc   = (const float*)d_in[6];
    const float* W_dec   = (const float*)d_in[7];
    const float* b_dec   = (const float*)d_in[8];
    const float* W_mem   = (const float*)d_in[9];
    const float* W_query = (const float*)d_in[10];
    const float* v_att   = (const float*)d_in[11];
    const float* W_attn  = (const float*)d_in[12];
    const float* W_proj  = (const float*)d_in[13];
    float* out = (float*)d_out;

    const int smemE = (768*PX + 512*PX + 256) * 4;                   //  93,184 B
    const int smemD = (1280*PX + 512*PX + 256) * 4;                  // 130,048 B
    const int smemK = (2*16*(NH + 4)) * 4;                           //  66,048 B

    cudaFuncSetAttribute(enc_step,    cudaFuncAttributeMaxDynamicSharedMemorySize, smemE);
    cudaFuncSetAttribute(dec_lstm,    cudaFuncAttributeMaxDynamicSharedMemorySize, smemD);
    cudaFuncSetAttribute(keys_kernel, cudaFuncAttributeMaxDynamicSharedMemorySize, smemK);
    cudaFuncSetAttribute(proj_hmma,   cudaFuncAttributeMaxDynamicSharedMemorySize, PROJ_SMEM);

    prep_kernel<<<256, 256>>>(enc_in, dec_in, dlen, emb);
    permW_kernel<<<512, 256>>>(W_enc, W_dec);
    zero_kernel<<<dim3(88, 512), 256>>>((float4*)out);

    for (int t = 0; t < NTE; t++)
        enc_step<<<128, 512, smemE>>>(b_enc, elen, t);

    keys_kernel<<<dim3(32, 64), 256, smemK>>>(W_mem);

    for (int t = 0; t < NTD; t++) {
        dec_lstm<<<128, 512, smemD>>>(b_dec, t);
        dec_pq<<<128, 256>>>(W_query, t);
        dec_att<<<16, 512>>>(v_att, elen, t);
        dec_attn2<<<128, 256>>>(W_attn, t);
    }

    proj_hmma<<<dim3(4, 704), 256, PROJ_SMEM>>>(W_proj, out);
}

// round 12
// speedup vs baseline: 1.4932x; 1.0099x over previous
#include <cuda_runtime.h>
#include <cuda_bf16.h>
#include <math.h>
#include <stdint.h>

#define NB 16
#define NTE 64
#define NTD 32
#define NE 256
#define NH 512
#define NG 2048
#define NV 90000
#define NEGV (-1e9f)
#define PX 18

typedef unsigned long long u64;

// ---------------- device scratch ----------------
__device__ float g_qemb[NB*NTE*NE];
__device__ float g_remb[NB*NTD*NE];
__device__ float g_h[2][NB*NH];
__device__ float g_c[2][NB*NH];
__device__ float g_attn[NB*NH];
__device__ float g_encout[NB*NTE*NH];
__device__ float g_keys[NB*NTE*NH];
__device__ float g_pq[NB*NH];
__device__ float g_ctx[NB*NH];
__device__ int   g_outrow[NB*NTD];
__device__ int   g_rowpos[NB*NTD];
__device__ int   g_nrows;
// per-CTA-contiguous weight layouts
__device__ float g_W3e[128*768*16];    // [c][k][gl]
__device__ float g_W3d[128*1280*16];   // [c][k][gl]
__device__ float g_Wq2[128*512*4];     // [c][k][j]
__device__ float g_Wa2[128*1024*4];    // [c][k][j]
__device__ __nv_bfloat16 g_Ahi[512*NH];
__device__ __nv_bfloat16 g_Alo[512*NH];

// ---------------- fast math ----------------
__device__ __forceinline__ float fsig(float x) {
    return __fdividef(1.f, 1.f + __expf(-x));
}
__device__ __forceinline__ float ftanh(float x) {
    x = fminf(fmaxf(x, -15.f), 15.f);
    float a = __expf(2.f * x);
    return __fdividef(a - 1.f, a + 1.f);
}

__device__ __forceinline__ u64 packdup(float v) {
    u64 r;
    asm("mov.b64 %0, {%1, %1};" : "=l"(r) : "r"(__float_as_uint(v)));
    return r;
}
__device__ __forceinline__ void fma2(u64& d, u64 a, u64 b) {
    asm("fma.rn.f32x2 %0, %1, %2, %0;" : "+l"(d) : "l"(a), "l"(b));
}
__device__ __forceinline__ void unpack2(u64 v, float& lo, float& hi) {
    unsigned l, h;
    asm("mov.b64 {%0, %1}, %2;" : "=r"(l), "=r"(h) : "l"(v));
    lo = __uint_as_float(l); hi = __uint_as_float(h);
}
__device__ __forceinline__ uint32_t smem_u32(const void* p) {
    uint32_t a;
    asm("{ .reg .u64 t; cvta.to.shared.u64 t, %1; cvt.u32.u64 %0, t; }" : "=r"(a) : "l"(p));
    return a;
}

// ---------------- prep ----------------
__global__ void prep_kernel(const int* __restrict__ enc_in, const int* __restrict__ dec_in,
                            const int* __restrict__ dlen, const float* __restrict__ emb)
{
    int idx = blockIdx.x * blockDim.x + threadIdx.x;
    int stride = gridDim.x * blockDim.x;
    for (int i = idx; i < NB*NTE*NE; i += stride) {
        int e = i & (NE - 1); int bt = i >> 8;
        g_qemb[i] = emb[(size_t)enc_in[bt] * NE + e];
    }
    for (int i = idx; i < NB*NTD*NE; i += stride) {
        int e = i & (NE - 1); int bt = i >> 8;
        g_remb[i] = emb[(size_t)dec_in[bt] * NE + e];
    }
    for (int i = idx; i < NB*NH; i += stride) {
        g_h[0][i] = 0.f; g_c[0][i] = 0.f; g_attn[i] = 0.f;
    }
    __nv_bfloat16 z = __float2bfloat16(0.f);
    for (int i = idx; i < 512*NH; i += stride) { g_Ahi[i] = z; g_Alo[i] = z; }
    if (idx == 0) {
        int n = 0;
        for (int b = 0; b < NB; b++) {
            int L = dlen[b]; if (L > NTD) L = NTD; if (L < 0) L = 0;
            for (int t2 = 0; t2 < NTD; t2++) {
                if (t2 < L) { g_outrow[n] = b*NTD + t2; g_rowpos[b*NTD + t2] = n; n++; }
                else g_rowpos[b*NTD + t2] = -1;
            }
        }
        g_nrows = n;
    }
}

// ---------------- permute weights to per-CTA-contiguous layouts ----------------
// W3[(c*K + k)*16 + gl] = W[k*2048 + q*512 + c*4 + jl],  gl = jl*4 + q
__global__ void permW_kernel(const float* __restrict__ We, const float* __restrict__ Wd,
                             const float* __restrict__ Wq, const float* __restrict__ Wa)
{
    int idx = blockIdx.x * blockDim.x + threadIdx.x;
    int stride = gridDim.x * blockDim.x;
    for (int i = idx; i < 128*768*16; i += stride) {
        int gl = i & 15, r = i >> 4;
        int k = r % 768, c = r / 768;
        int jl = gl >> 2, q = gl & 3;
        g_W3e[i] = We[(size_t)k*NG + q*NH + (c << 2) + jl];
    }
    for (int i = idx; i < 128*1280*16; i += stride) {
        int gl = i & 15, r = i >> 4;
        int k = r % 1280, c = r / 1280;
        int jl = gl >> 2, q = gl & 3;
        g_W3d[i] = Wd[(size_t)k*NG + q*NH + (c << 2) + jl];
    }
    for (int i = idx; i < 128*512*4; i += stride) {
        int j = i & 3, r = i >> 2;
        int k = r & 511, c = r >> 9;
        g_Wq2[i] = Wq[(size_t)k*NH + (c << 2) + j];
    }
    for (int i = idx; i < 128*1024*4; i += stride) {
        int j = i & 3, r = i >> 2;
        int k = r & 1023, c = r >> 10;
        g_Wa2[i] = Wa[(size_t)k*NH + (c << 2) + j];
    }
}

// zero only invalid output rows
__global__ void zero_kernel(float4* __restrict__ out)
{
    int row = blockIdx.y;
    if (g_rowpos[row] >= 0) return;
    int pos = blockIdx.x * 256 + threadIdx.x;
    if (pos < 22500)
        out[(size_t)row * 22500 + pos] = make_float4(0.f, 0.f, 0.f, 0.f);
}

// ---------------- encoder step: 128 CTAs x 512 thr ----------------
__global__ void __launch_bounds__(512, 1)
enc_step(const float* __restrict__ bias, const int* __restrict__ elen, int t)
{
    extern __shared__ float sm[];
    float* xs = sm;                 // [768][PX]
    float* zp = sm + 768*PX;        // [512][PX]
    float* zz = zp + 512*PX;        // [256]

    int tid = threadIdx.x;
    int c = blockIdx.x;
    int gl = tid & 15, s = tid >> 4;
    int k0 = s * 24;

    const float* h_in  = g_h[t & 1];
    const float* c_in  = g_c[t & 1];
    float* h_out = g_h[(t + 1) & 1];
    float* c_out = g_c[(t + 1) & 1];

    // weight loads first: contiguous per-CTA block, max MLP
    float wreg[24];
    {
        const float* Wp = g_W3e + ((size_t)c*768 + k0)*16 + gl;
        #pragma unroll
        for (int kk = 0; kk < 24; kk++) wreg[kk] = __ldg(Wp + kk*16);
    }

    #pragma unroll
    for (int b = 0; b < 16; b++)
        for (int k = tid; k < 768; k += 512) {
            float v = (k < NE) ? g_qemb[(b*NTE + t)*NE + k] : h_in[b*NH + (k - NE)];
            xs[k*PX + b] = v;
        }
    __syncthreads();

    u64 acc[8];
    #pragma unroll
    for (int p = 0; p < 8; p++) acc[p] = 0ULL;
    #pragma unroll
    for (int kk = 0; kk < 24; kk++) {
        u64 w2 = packdup(wreg[kk]);
        const u64* xk = (const u64*)(xs + (k0 + kk)*PX);
        #pragma unroll
        for (int p = 0; p < 8; p++) fma2(acc[p], xk[p], w2);
    }
    #pragma unroll
    for (int p = 0; p < 8; p++) {
        float lo, hi; unpack2(acc[p], lo, hi);
        zp[tid*PX + 2*p]   = lo;
        zp[tid*PX + 2*p+1] = hi;
    }
    __syncthreads();

    if (tid < 256) {
        int g2 = tid >> 4, b = tid & 15;
        float sum = 0.f;
        #pragma unroll
        for (int ss = 0; ss < 32; ss++) sum += zp[(g2 + 16*ss)*PX + b];
        zz[g2*16 + b] = sum + bias[(g2 & 3)*NH + (c << 2) + (g2 >> 2)];
    }
    __syncthreads();

    if (tid < 64) {
        int jl = tid >> 4, b = tid & 15;
        int jg = (c << 2) + jl;
        float iv = zz[(jl*4 + 0)*16 + b];
        float jv = zz[(jl*4 + 1)*16 + b];
        float fv = zz[(jl*4 + 2)*16 + b];
        float ov = zz[(jl*4 + 3)*16 + b];
        float cold = c_in[b*NH + jg];
        float c2 = cold * fsig(fv + 1.f) + fsig(iv) * ftanh(jv);
        float h2 = ftanh(c2) * fsig(ov);
        bool valid = t < elen[b];
        float hold = xs[(NE + jg)*PX + b];
        h_out[b*NH + jg] = valid ? h2 : hold;
        c_out[b*NH + jg] = valid ? c2 : cold;
        g_encout[((size_t)b*NTE + t)*NH + jg] = valid ? h2 : 0.f;
    }
}

// ---------------- keys = enc_out @ W_mem ----------------
__global__ void keys_kernel(const float* __restrict__ Wm)
{
    extern __shared__ float sm[];
    const int KX = NH, KP = NH + 4;
    float* xs = sm;
    float* ws = sm + 16*KP;
    int tid = threadIdx.x;
    int cn = blockIdx.x;
    int cr = blockIdx.y;

    for (int i = tid; i < 16*KX; i += 256) {
        int rl = i >> 9, k = i & 511;
        xs[rl*KP + k] = g_encout[(cr*16 + rl)*NH + k];
    }
    for (int i = tid; i < 16*KX; i += 256) {
        int k = i >> 4, nl = i & 15;
        ws[nl*KP + k] = Wm[k*NH + cn*16 + nl];
    }
    __syncthreads();

    int nl = tid & 15, rl = tid >> 4;
    float a0 = 0.f, a1 = 0.f, a2 = 0.f, a3 = 0.f;
    const float* xp = xs + rl*KP;
    const float* wp = ws + nl*KP;
    #pragma unroll 8
    for (int k = 0; k < KX; k += 4) {
        float4 a = *(const float4*)(xp + k);
        float4 w = *(const float4*)(wp + k);
        a0 = fmaf(a.x, w.x, a0);
        a1 = fmaf(a.y, w.y, a1);
        a2 = fmaf(a.z, w.z, a2);
        a3 = fmaf(a.w, w.w, a3);
    }
    g_keys[(cr*16 + rl)*NH + cn*16 + nl] = (a0 + a1) + (a2 + a3);
}

// ---------------- decoder LSTM step: 128 CTAs x 512 thr ----------------
__global__ void __launch_bounds__(512, 1)
dec_lstm(const float* __restrict__ bias, int t)
{
    extern __shared__ float sm[];
    float* xs = sm;                 // [1280][PX]
    float* zp = sm + 1280*PX;       // [512][PX]
    float* zz = zp + 512*PX;        // [256]

    int tid = threadIdx.x;
    int c = blockIdx.x;
    int gl = tid & 15, s = tid >> 4;
    int k0 = s * 40;

    const float* h_in  = g_h[t & 1];
    const float* c_in  = g_c[t & 1];
    float* h_out = g_h[(t + 1) & 1];
    float* c_out = g_c[(t + 1) & 1];

    float wreg[40];
    {
        const float* Wp = g_W3d + ((size_t)c*1280 + k0)*16 + gl;
        #pragma unroll
        for (int kk = 0; kk < 40; kk++) wreg[kk] = __ldg(Wp + kk*16);
    }

    #pragma unroll
    for (int b = 0; b < 16; b++)
        for (int k = tid; k < 1280; k += 512) {
            float v;
            if (k < NE)           v = g_remb[(b*NTD + t)*NE + k];
            else if (k < NE + NH) v = g_attn[b*NH + (k - NE)];
            else                  v = h_in[b*NH + (k - NE - NH)];
            xs[k*PX + b] = v;
        }
    __syncthreads();

    u64 acc[8];
    #pragma unroll
    for (int p = 0; p < 8; p++) acc[p] = 0ULL;
    #pragma unroll
    for (int kk = 0; kk < 40; kk++) {
        u64 w2 = packdup(wreg[kk]);
        const u64* xk = (const u64*)(xs + (k0 + kk)*PX);
        #pragma unroll
        for (int p = 0; p < 8; p++) fma2(acc[p], xk[p], w2);
    }
    #pragma unroll
    for (int p = 0; p < 8; p++) {
        float lo, hi; unpack2(acc[p], lo, hi);
        zp[tid*PX + 2*p]   = lo;
        zp[tid*PX + 2*p+1] = hi;
    }
    __syncthreads();

    if (tid < 256) {
        int g2 = tid >> 4, b = tid & 15;
        float sum = 0.f;
        #pragma unroll
        for (int ss = 0; ss < 32; ss++) sum += zp[(g2 + 16*ss)*PX + b];
        zz[g2*16 + b] = sum + bias[(g2 & 3)*NH + (c << 2) + (g2 >> 2)];
    }
    __syncthreads();

    if (tid < 64) {
        int jl = tid >> 4, b = tid & 15;
        int jg = (c << 2) + jl;
        float iv = zz[(jl*4 + 0)*16 + b];
        float jv = zz[(jl*4 + 1)*16 + b];
        float fv = zz[(jl*4 + 2)*16 + b];
        float ov = zz[(jl*4 + 3)*16 + b];
        float cold = c_in[b*NH + jg];
        float c2 = cold * fsig(fv + 1.f) + fsig(iv) * ftanh(jv);
        float h2 = ftanh(c2) * fsig(ov);
        h_out[b*NH + jg] = h2;
        c_out[b*NH + jg] = c2;
    }
}

// ---------------- pq = h2 @ Wq : 128 CTAs x 256 thr ----------------
__global__ void __launch_bounds__(256, 2)
dec_pq(int t)
{
    __shared__ float zp[256*4];
    int tid = threadIdx.x;
    int c = blockIdx.x;
    int n0 = c * 4;
    int bq = tid & 15, ks = tid >> 4;
    const float* h2 = g_h[(t + 1) & 1];

    const float* hp = h2 + bq*NH + ks*32;
    const float4* wq4 = (const float4*)(g_Wq2 + (size_t)c*2048);
    float a0 = 0.f, a1 = 0.f, a2 = 0.f, a3 = 0.f;
    #pragma unroll
    for (int kk = 0; kk < 32; kk++) {
        float x = hp[kk];
        float4 w = __ldg(wq4 + ks*32 + kk);
        a0 = fmaf(x, w.x, a0);
        a1 = fmaf(x, w.y, a1);
        a2 = fmaf(x, w.z, a2);
        a3 = fmaf(x, w.w, a3);
    }
    zp[tid*4 + 0] = a0; zp[tid*4 + 1] = a1;
    zp[tid*4 + 2] = a2; zp[tid*4 + 3] = a3;
    __syncthreads();

    if (tid < 64) {
        int bb = tid >> 2, j = tid & 3;
        float sv = 0.f;
        #pragma unroll
        for (int ss = 0; ss < 16; ss++) sv += zp[(bb + 16*ss)*4 + j];
        g_pq[bb*NH + n0 + j] = sv;
    }
}

// ---------------- scores + softmax + ctx : 16 CTAs x 512 thr ----------------
__global__ void __launch_bounds__(512, 1)
dec_att(const float* __restrict__ vatt, const int* __restrict__ elen, int t)
{
    __shared__ float pqv[NH];
    __shared__ float vsv[NH];
    __shared__ float scv[NTE];

    int tid = threadIdx.x;
    int b = blockIdx.x;

    pqv[tid] = g_pq[b*NH + tid];
    vsv[tid] = vatt[tid];
    __syncthreads();

    int w = tid >> 5, l = tid & 31;
    int len = elen[b];
    #pragma unroll
    for (int r = 0; r < 4; r++) {
        int te = w*4 + r;
        const float* kp = g_keys + ((size_t)b*NTE + te)*NH;
        float p = 0.f;
        #pragma unroll
        for (int j = 0; j < 16; j++) {
            int h = l + 32*j;
            p += vsv[h] * ftanh(kp[h] + pqv[h]);
        }
        #pragma unroll
        for (int off = 16; off > 0; off >>= 1) p += __shfl_xor_sync(0xffffffffu, p, off);
        if (l == 0) scv[te] = (te < len) ? p : NEGV;
    }
    __syncthreads();

    if (tid < 32) {
        float a = scv[tid], b2 = scv[tid + 32];
        float m = fmaxf(a, b2);
        #pragma unroll
        for (int off = 16; off > 0; off >>= 1) m = fmaxf(m, __shfl_xor_sync(0xffffffffu, m, off));
        float e1 = __expf(a - m), e2 = __expf(b2 - m);
        float ssum = e1 + e2;
        #pragma unroll
        for (int off = 16; off > 0; off >>= 1) ssum += __shfl_xor_sync(0xffffffffu, ssum, off);
        float inv = __fdividef(1.f, ssum);
        scv[tid] = e1 * inv; scv[tid + 32] = e2 * inv;
    }
    __syncthreads();

    {
        int h = tid;
        float acc = 0.f;
        const float* ep = g_encout + (size_t)b*NTE*NH + h;
        #pragma unroll 8
        for (int te = 0; te < NTE; te++)
            acc = fmaf(scv[te], ep[(size_t)te*NH], acc);
        g_ctx[b*NH + h] = acc;
    }
}

// ---------------- attn2 = [h2|ctx] @ Wa : 128 CTAs x 256 thr ----------------
__global__ void __launch_bounds__(256, 2)
dec_attn2(int t)
{
    __shared__ float zp[256*4];
    int tid = threadIdx.x;
    int c = blockIdx.x;
    int n0 = c * 4;
    int bq = tid & 15, ks = tid >> 4;
    const float* h2 = g_h[(t + 1) & 1];

    const float* src = (ks < 8) ? (h2 + bq*NH + ks*64)
                                : (g_ctx + bq*NH + (ks - 8)*64);
    const float4* wa4 = (const float4*)(g_Wa2 + (size_t)c*4096);
    float a0 = 0.f, a1 = 0.f, a2 = 0.f, a3 = 0.f;
    #pragma unroll
    for (int kk = 0; kk < 64; kk++) {
        float x = src[kk];
        float4 w = __ldg(wa4 + ks*64 + kk);
        a0 = fmaf(x, w.x, a0);
        a1 = fmaf(x, w.y, a1);
        a2 = fmaf(x, w.z, a2);
        a3 = fmaf(x, w.w, a3);
    }
    zp[tid*4 + 0] = a0; zp[tid*4 + 1] = a1;
    zp[tid*4 + 2] = a2; zp[tid*4 + 3] = a3;
    __syncthreads();

    if (tid < 64) {
        int bb = tid >> 2, j = tid & 3;
        float sv = 0.f;
        #pragma unroll
        for (int ss = 0; ss < 16; ss++) sv += zp[(bb + 16*ss)*4 + j];
        g_attn[bb*NH + n0 + j] = sv;
        int m = g_rowpos[bb*NTD + t];
        if (m >= 0) {
            __nv_bfloat16 hi = __float2bfloat16(sv);
            g_Ahi[m*NH + n0 + j] = hi;
            g_Alo[m*NH + n0 + j] = __float2bfloat16(sv - __bfloat162float(hi));
        }
    }
}

// ---------------- HMMA projection with in-kernel W conversion ----------------
#define PR_LDA 72
#define PROJ_SMEM (4*128*PR_LDA*2)

__device__ __forceinline__ void ldmA(uint32_t* a, uint32_t addr) {
    asm volatile("ldmatrix.sync.aligned.m8n8.x4.shared.b16 {%0,%1,%2,%3}, [%4];"
                 : "=r"(a[0]), "=r"(a[1]), "=r"(a[2]), "=r"(a[3]) : "r"(addr));
}
__device__ __forceinline__ void ldmB(uint32_t* b, uint32_t addr) {
    asm volatile("ldmatrix.sync.aligned.m8n8.x2.shared.b16 {%0,%1}, [%2];"
                 : "=r"(b[0]), "=r"(b[1]) : "r"(addr));
}
__device__ __forceinline__ void mma16816(float* c, const uint32_t* a, const uint32_t* b) {
    asm volatile("mma.sync.aligned.m16n8k16.row.col.f32.bf16.bf16.f32 "
                 "{%0,%1,%2,%3}, {%4,%5,%6,%7}, {%8,%9}, {%0,%1,%2,%3};"
                 : "+f"(c[0]), "+f"(c[1]), "+f"(c[2]), "+f"(c[3])
                 : "r"(a[0]), "r"(a[1]), "r"(a[2]), "r"(a[3]), "r"(b[0]), "r"(b[1]));
}

__global__ void __launch_bounds__(256, 1)
proj_hmma(const float* __restrict__ Wp, float* __restrict__ out)
{
    extern __shared__ __nv_bfloat16 smb[];
    __nv_bfloat16* sAhi = smb;
    __nv_bfloat16* sAlo = smb + 128*PR_LDA;
    __nv_bfloat16* sBhi = smb + 2*128*PR_LDA;
    __nv_bfloat16* sBlo = smb + 3*128*PR_LDA;

    int m0 = blockIdx.x * 128;
    int n0 = blockIdx.y * 128;
    int nr = g_nrows;
    if (m0 >= nr) return;

    int tid = threadIdx.x;
    int wid = tid >> 5, lane = tid & 31;
    int m0w = (wid >> 2) * 64;
    int n0w = (wid & 3) * 32;

    uint32_t sb = smem_u32(smb);
    uint32_t aAhi = sb, aAlo = sb + 128*PR_LDA*2, aBhi = sb + 2*128*PR_LDA*2, aBlo = sb + 3*128*PR_LDA*2;

    float c[4][4][4];
    #pragma unroll
    for (int i = 0; i < 4; i++)
        #pragma unroll
        for (int j = 0; j < 4; j++)
            #pragma unroll
            for (int q = 0; q < 4; q++) c[i][j][q] = 0.f;

    for (int ch = 0; ch < 8; ch++) {
        int k0 = ch * 64;
        for (int i = tid; i < 1024; i += 256) {
            int m = i >> 3, kb = i & 7;
            size_t go = (size_t)(m0 + m)*NH + k0 + kb*8;
            int so = m*PR_LDA + kb*8;
            *(uint4*)&sAhi[so] = *(const uint4*)&g_Ahi[go];
            *(uint4*)&sAlo[so] = *(const uint4*)&g_Alo[go];
        }
        for (int i = tid; i < 4096; i += 256) {
            int n = i & 127, kkp = i >> 7;
            int kk = kkp * 2;
            int nn = n0 + n;
            float w0 = 0.f, w1 = 0.f;
            if (nn < NV) {
                w0 = Wp[(size_t)(k0 + kk)*NV + nn];
                w1 = Wp[(size_t)(k0 + kk + 1)*NV + nn];
            }
            __nv_bfloat16 h0 = __float2bfloat16(w0);
            __nv_bfloat16 h1 = __float2bfloat16(w1);
            float r0 = w0 - __bfloat162float(h0);
            float r1 = w1 - __bfloat162float(h1);
            __nv_bfloat16 l0 = __float2bfloat16(r0);
            __nv_bfloat16 l1 = __float2bfloat16(r1);
            uint32_t hv = (uint32_t)__bfloat16_as_ushort(h0) |
                          ((uint32_t)__bfloat16_as_ushort(h1) << 16);
            uint32_t lv = (uint32_t)__bfloat16_as_ushort(l0) |
                          ((uint32_t)__bfloat16_as_ushort(l1) << 16);
            int so = n*PR_LDA + kk;
            *(uint32_t*)&sBhi[so] = hv;
            *(uint32_t*)&sBlo[so] = lv;
        }
        __syncthreads();

        #pragma unroll
        for (int ksp = 0; ksp < 4; ksp++) {
            int kp = ksp * 16;
            uint32_t ahi[4][4], alo[4][4], bhi[4][2], blo[4][2];
            #pragma unroll
            for (int mt = 0; mt < 4; mt++) {
                uint32_t off = ((m0w + mt*16 + (lane & 15)) * PR_LDA + kp + ((lane >> 4) << 3)) * 2;
                ldmA(ahi[mt], aAhi + off);
                ldmA(alo[mt], aAlo + off);
            }
            #pragma unroll
            for (int nt = 0; nt < 4; nt++) {
                uint32_t off = ((n0w + nt*8 + (lane & 7)) * PR_LDA + kp + (((lane >> 3) & 1) << 3)) * 2;
                ldmB(bhi[nt], aBhi + off);
                ldmB(blo[nt], aBlo + off);
            }
            #pragma unroll
            for (int mt = 0; mt < 4; mt++)
                #pragma unroll
                for (int nt = 0; nt < 4; nt++) {
                    mma16816(c[mt][nt], ahi[mt], bhi[nt]);
                    mma16816(c[mt][nt], ahi[mt], blo[nt]);
                    mma16816(c[mt][nt], alo[mt], bhi[nt]);
                }
        }
        __syncthreads();
    }

    int rg = lane >> 2, cg = (lane & 3) * 2;
    #pragma unroll
    for (int mt = 0; mt < 4; mt++) {
        #pragma unroll
        for (int half = 0; half < 2; half++) {
            int mloc = m0w + mt*16 + rg + half*8;
            int m = m0 + mloc;
            if (m < nr) {
                int orow = g_outrow[m];
                float* obase = out + (size_t)orow*NV;
                #pragma unroll
                for (int nt = 0; nt < 4; nt++) {
                    int nn = n0 + n0w + nt*8 + cg;
                    float v0 = c[mt][nt][half*2 + 0];
                    float v1 = c[mt][nt][half*2 + 1];
                    if (nn + 1 < NV) {
                        *(float2*)(obase + nn) = make_float2(v0, v1);
                    } else if (nn < NV) {
                        obase[nn] = v0;
                    }
                }
            }
        }
    }
}

// ---------------- launch ----------------
extern "C" void kernel_launch(void* const* d_in, const int* in_sizes, int n_in,
                              void* d_out, int out_size)
{
    const int*   enc_in  = (const int*)d_in[0];
    const int*   dec_in  = (const int*)d_in[1];
    const int*   elen    = (const int*)d_in[2];
    const int*   dlen    = (const int*)d_in[3];
    const float* emb     = (const float*)d_in[4];
    const float* W_enc   = (const float*)d_in[5];
    const float* b_enc   = (const float*)d_in[6];
    const float* W_dec   = (const float*)d_in[7];
    const float* b_dec   = (const float*)d_in[8];
    const float* W_mem   = (const float*)d_in[9];
    const float* W_query = (const float*)d_in[10];
    const float* v_att   = (const float*)d_in[11];
    const float* W_attn  = (const float*)d_in[12];
    const float* W_proj  = (const float*)d_in[13];
    float* out = (float*)d_out;

    const int smemE = (768*PX + 512*PX + 256) * 4;                   //  93,184 B
    const int smemD = (1280*PX + 512*PX + 256) * 4;                  // 130,048 B
    const int smemK = (2*16*(NH + 4)) * 4;                           //  66,048 B

    cudaFuncSetAttribute(enc_step,    cudaFuncAttributeMaxDynamicSharedMemorySize, smemE);
    cudaFuncSetAttribute(dec_lstm,    cudaFuncAttributeMaxDynamicSharedMemorySize, smemD);
    cudaFuncSetAttribute(keys_kernel, cudaFuncAttributeMaxDynamicSharedMemorySize, smemK);
    cudaFuncSetAttribute(proj_hmma,   cudaFuncAttributeMaxDynamicSharedMemorySize, PROJ_SMEM);

    prep_kernel<<<256, 256>>>(enc_in, dec_in, dlen, emb);
    permW_kernel<<<1024, 256>>>(W_enc, W_dec, W_query, W_attn);
    zero_kernel<<<dim3(88, 512), 256>>>((float4*)out);

    for (int t = 0; t < NTE; t++)
        enc_step<<<128, 512, smemE>>>(b_enc, elen, t);

    keys_kernel<<<dim3(32, 64), 256, smemK>>>(W_mem);

    for (int t = 0; t < NTD; t++) {
        dec_lstm<<<128, 512, smemD>>>(b_dec, t);
        dec_pq<<<128, 256>>>(t);
        dec_att<<<16, 512>>>(v_att, elen, t);
        dec_attn2<<<128, 256>>>(t);
    }

    proj_hmma<<<dim3(4, 704), 256, PROJ_SMEM>>>(W_proj, out);
}